// round 10
// baseline (speedup 1.0000x reference)
#include <cuda_runtime.h>
#include <cuda_bf16.h>
#include <cstdint>

#define DIM 80
#define DD 6400
#define D3 512000
#define NPTS 200000
#define NPAD 200064   // 1563 * 128

typedef unsigned long long u64;
typedef unsigned int u32;

// ---------------------------------------------------------------------------
// Device scratch (no allocations in kernel_launch)
// ---------------------------------------------------------------------------
__device__ __nv_bfloat16 g_xhi[D3 * 32];
__device__ __nv_bfloat16 g_xlo[D3 * 32];
__device__ __nv_bfloat16 g_f1hi[D3 * 64];
__device__ __nv_bfloat16 g_f1lo[D3 * 64];
__device__ float         g_f2[D3 * 64];
__device__ __nv_bfloat16 g_w1hi[14 * 64 * 64], g_w1lo[14 * 64 * 64];
__device__ __nv_bfloat16 g_w2hi[27 * 64 * 64], g_w2lo[27 * 64 * 64];
// MLP
__device__ __nv_bfloat16 g_h1hi[(size_t)NPAD * 256], g_h1lo[(size_t)NPAD * 256];
__device__ __nv_bfloat16 g_h2hi[(size_t)NPAD * 256], g_h2lo[(size_t)NPAD * 256];
__device__ float         g_h3[(size_t)NPAD * 64];
__device__ __nv_bfloat16 g_mw1hi[256 * 64],  g_mw1lo[256 * 64];
__device__ __nv_bfloat16 g_mw2hi[256 * 256], g_mw2lo[256 * 256];
__device__ __nv_bfloat16 g_mw3hi[64 * 256],  g_mw3lo[64 * 256];

__device__ __forceinline__ u32 pkbf(__nv_bfloat16 a, __nv_bfloat16 b) {
    return (u32)__bfloat16_as_ushort(a) | ((u32)__bfloat16_as_ushort(b) << 16);
}

__device__ __forceinline__ void mma16816(float* d, const u32* a, const u32* b) {
    asm volatile(
        "mma.sync.aligned.m16n8k16.row.col.f32.bf16.bf16.f32 "
        "{%0,%1,%2,%3}, {%4,%5,%6,%7}, {%8,%9}, {%0,%1,%2,%3};"
        : "+f"(d[0]), "+f"(d[1]), "+f"(d[2]), "+f"(d[3])
        : "r"(a[0]), "r"(a[1]), "r"(a[2]), "r"(a[3]), "r"(b[0]), "r"(b[1]));
}

// ---------------------------------------------------------------------------
// Prep kernels
// ---------------------------------------------------------------------------
__global__ void prep_img(const float* __restrict__ img) {
    int p = blockIdx.x * 256 + threadIdx.x;
    u32 hw[16], lw[16];
    #pragma unroll
    for (int c = 0; c < 32; c += 2) {
        float a = img[c * D3 + p];
        float b = img[(c + 1) * D3 + p];
        __nv_bfloat16 ah = __float2bfloat16_rn(a);
        __nv_bfloat16 al = __float2bfloat16_rn(a - __bfloat162float(ah));
        __nv_bfloat16 bh = __float2bfloat16_rn(b);
        __nv_bfloat16 bl = __float2bfloat16_rn(b - __bfloat162float(bh));
        hw[c >> 1] = pkbf(ah, bh);
        lw[c >> 1] = pkbf(al, bl);
    }
    uint4* oh = (uint4*)(g_xhi + (size_t)p * 32);
    uint4* ol = (uint4*)(g_xlo + (size_t)p * 32);
    #pragma unroll
    for (int q = 0; q < 4; q++) {
        oh[q] = make_uint4(hw[q*4], hw[q*4+1], hw[q*4+2], hw[q*4+3]);
        ol[q] = make_uint4(lw[q*4], lw[q*4+1], lw[q*4+2], lw[q*4+3]);
    }
}

__global__ void prep_w1(const float* __restrict__ w) {
    int idx = blockIdx.x * 256 + threadIdx.x;
    if (idx >= 14 * 4096) return;
    int j = idx >> 12, r = idx & 4095, o = r >> 6, k = r & 63;
    int t = k >> 5, c = k & 31, tp = 2 * j + t;
    float v = (tp <= 26) ? w[(o * 32 + c) * 27 + tp] : 0.f;
    __nv_bfloat16 h = __float2bfloat16_rn(v);
    g_w1hi[idx] = h;
    g_w1lo[idx] = __float2bfloat16_rn(v - __bfloat162float(h));
}
__global__ void prep_w2(const float* __restrict__ w) {
    int idx = blockIdx.x * 256 + threadIdx.x;
    if (idx >= 27 * 4096) return;
    int j = idx >> 12, r = idx & 4095, o = r >> 6, c = r & 63;
    float v = w[(o * 64 + c) * 27 + j];
    __nv_bfloat16 h = __float2bfloat16_rn(v);
    g_w2hi[idx] = h;
    g_w2lo[idx] = __float2bfloat16_rn(v - __bfloat162float(h));
}

__global__ void prep_wmlp(const float* __restrict__ src,
                          __nv_bfloat16* __restrict__ dhi,
                          __nv_bfloat16* __restrict__ dlo, int n) {
    int i = blockIdx.x * 256 + threadIdx.x;
    if (i >= n) return;
    float v = src[i];
    __nv_bfloat16 h = __float2bfloat16_rn(v);
    dhi[i] = h;
    dlo[i] = __float2bfloat16_rn(v - __bfloat162float(h));
}

// ---------------------------------------------------------------------------
// Conv via mma.sync, R10 geometry: CTA = 256 px x 64 oc, warps 4m x 2n,
// warp tile 64 x 32 (mt=4, NT=4). B fragments loaded once per k-step,
// A fragments per-mt. Fragment traffic per HMMA down 25% vs 32x32.
// ---------------------------------------------------------------------------
#define RSTR 144
#define CTAM 256
#define SA_HI 0
#define SA_LO (CTAM * RSTR)
#define SW_HI (2 * CTAM * RSTR)
#define SW_LO (2 * CTAM * RSTR + 64 * RSTR)
#define SMEM_CONV (2 * CTAM * RSTR + 2 * 64 * RSTR)   // 92160

template<int STAGE>
__global__ __launch_bounds__(256, 2) void conv_mma(const float* __restrict__ bias)
{
    constexpr int NCH = (STAGE == 1) ? 14 : 27;
    const __nv_bfloat16* Xhi = (STAGE == 1) ? g_xhi : g_f1hi;
    const __nv_bfloat16* Xlo = (STAGE == 1) ? g_xlo : g_f1lo;
    const __nv_bfloat16* Whi = (STAGE == 1) ? g_w1hi : g_w2hi;
    const __nv_bfloat16* Wlo = (STAGE == 1) ? g_w1lo : g_w2lo;

    extern __shared__ char smem[];
    const int tid = threadIdx.x;
    const int warp = tid >> 5, lane = tid & 31;
    const int p0 = blockIdx.x * CTAM;

    // staging: one thread per A row
    const int p = p0 + tid;
    const int z = p / DD;
    const int rr = p - z * DD;
    const int y = rr / DIM;
    const int x = rr - y * DIM;

    // mma roles: warp tile 64m x 32n
    const int wm = warp >> 1, wn = warp & 1;
    const int g = lane >> 2, tg = lane & 3;

    float acc[4][4][4];
    #pragma unroll
    for (int mt = 0; mt < 4; mt++)
        #pragma unroll
        for (int nt = 0; nt < 4; nt++)
            #pragma unroll
            for (int q = 0; q < 4; q++) acc[mt][nt][q] = 0.f;

    for (int j = 0; j < NCH; j++) {
        __syncthreads();
        // ---- stage A row tid (hi & lo), masked for padding ----
        if (STAGE == 1) {
            #pragma unroll
            for (int t = 0; t < 2; t++) {
                int tp = 2 * j + t;
                bool v = (tp <= 26);
                int kz = tp / 9, ky = (tp / 3) % 3, kx = tp % 3;
                v = v && (unsigned)(z + kz - 1) < 80u &&
                         (unsigned)(y + ky - 1) < 80u &&
                         (unsigned)(x + kx - 1) < 80u;
                int ps = p + (kz - 1) * DD + (ky - 1) * DIM + (kx - 1);
                const uint4* shi = (const uint4*)(Xhi + (size_t)ps * 32);
                const uint4* slo = (const uint4*)(Xlo + (size_t)ps * 32);
                const uint4 zero = make_uint4(0, 0, 0, 0);
                #pragma unroll
                for (int i = 0; i < 4; i++) {
                    u32 off = tid * RSTR + t * 64 + i * 16;
                    *(uint4*)(smem + SA_HI + off) = v ? shi[i] : zero;
                    *(uint4*)(smem + SA_LO + off) = v ? slo[i] : zero;
                }
            }
        } else {
            int kz = j / 9, ky = (j / 3) % 3, kx = j % 3;
            bool v = (unsigned)(z + kz - 1) < 80u &&
                     (unsigned)(y + ky - 1) < 80u &&
                     (unsigned)(x + kx - 1) < 80u;
            int ps = p + (kz - 1) * DD + (ky - 1) * DIM + (kx - 1);
            const uint4* shi = (const uint4*)(Xhi + (size_t)ps * 64);
            const uint4* slo = (const uint4*)(Xlo + (size_t)ps * 64);
            const uint4 zero = make_uint4(0, 0, 0, 0);
            #pragma unroll
            for (int i = 0; i < 8; i++) {
                u32 off = tid * RSTR + i * 16;
                *(uint4*)(smem + SA_HI + off) = v ? shi[i] : zero;
                *(uint4*)(smem + SA_LO + off) = v ? slo[i] : zero;
            }
        }
        // ---- stage W (64 rows x 128B, hi & lo) ----
        {
            const uint4* wh = (const uint4*)(Whi + j * 4096);
            const uint4* wl = (const uint4*)(Wlo + j * 4096);
            #pragma unroll
            for (int u = tid; u < 512; u += 256) {
                u32 off = (u >> 3) * RSTR + (u & 7) * 16;
                *(uint4*)(smem + SW_HI + off) = wh[u];
                *(uint4*)(smem + SW_LO + off) = wl[u];
            }
        }
        __syncthreads();

        // ---- compute: 4 k16 steps; B frags once, A frags per mt ----
        #pragma unroll
        for (int ks = 0; ks < 4; ks++) {
            u32 bh[4][2], bl[4][2];
            #pragma unroll
            for (int nt = 0; nt < 4; nt++) {
                u32 base = (wn * 32 + nt * 8 + g) * RSTR + ks * 32 + tg * 4;
                bh[nt][0] = *(const u32*)(smem + SW_HI + base);
                bh[nt][1] = *(const u32*)(smem + SW_HI + base + 16);
                bl[nt][0] = *(const u32*)(smem + SW_LO + base);
                bl[nt][1] = *(const u32*)(smem + SW_LO + base + 16);
            }
            #pragma unroll
            for (int mt = 0; mt < 4; mt++) {
                u32 ah[4], al[4];
                u32 base = (wm * 64 + mt * 16 + g) * RSTR + ks * 32 + tg * 4;
                ah[0] = *(const u32*)(smem + SA_HI + base);
                ah[1] = *(const u32*)(smem + SA_HI + base + 8 * RSTR);
                ah[2] = *(const u32*)(smem + SA_HI + base + 16);
                ah[3] = *(const u32*)(smem + SA_HI + base + 8 * RSTR + 16);
                al[0] = *(const u32*)(smem + SA_LO + base);
                al[1] = *(const u32*)(smem + SA_LO + base + 8 * RSTR);
                al[2] = *(const u32*)(smem + SA_LO + base + 16);
                al[3] = *(const u32*)(smem + SA_LO + base + 8 * RSTR + 16);
                #pragma unroll
                for (int nt = 0; nt < 4; nt++) {
                    mma16816(acc[mt][nt], ah, bh[nt]);
                    mma16816(acc[mt][nt], ah, bl[nt]);
                    mma16816(acc[mt][nt], al, bh[nt]);
                }
            }
        }
    }

    // ---- epilogue: bias + ReLU ----
    #pragma unroll
    for (int mt = 0; mt < 4; mt++) {
        #pragma unroll
        for (int nt = 0; nt < 4; nt++) {
            const int n = wn * 32 + nt * 8 + tg * 2;
            const float b0 = __ldg(bias + n), b1 = __ldg(bias + n + 1);
            const int pixA = p0 + wm * 64 + mt * 16 + g;
            const int pixB = pixA + 8;
            float v0 = fmaxf(acc[mt][nt][0] + b0, 0.f);
            float v1 = fmaxf(acc[mt][nt][1] + b1, 0.f);
            float v2 = fmaxf(acc[mt][nt][2] + b0, 0.f);
            float v3 = fmaxf(acc[mt][nt][3] + b1, 0.f);
            if (STAGE == 1) {
                __nv_bfloat16 h0 = __float2bfloat16_rn(v0);
                __nv_bfloat16 h1 = __float2bfloat16_rn(v1);
                __nv_bfloat16 h2 = __float2bfloat16_rn(v2);
                __nv_bfloat16 h3 = __float2bfloat16_rn(v3);
                *(u32*)(g_f1hi + (size_t)pixA * 64 + n) = pkbf(h0, h1);
                *(u32*)(g_f1hi + (size_t)pixB * 64 + n) = pkbf(h2, h3);
                *(u32*)(g_f1lo + (size_t)pixA * 64 + n) =
                    pkbf(__float2bfloat16_rn(v0 - __bfloat162float(h0)),
                         __float2bfloat16_rn(v1 - __bfloat162float(h1)));
                *(u32*)(g_f1lo + (size_t)pixB * 64 + n) =
                    pkbf(__float2bfloat16_rn(v2 - __bfloat162float(h2)),
                         __float2bfloat16_rn(v3 - __bfloat162float(h3)));
            } else {
                *(float2*)(g_f2 + (size_t)pixA * 64 + n) = make_float2(v0, v1);
                *(float2*)(g_f2 + (size_t)pixB * 64 + n) = make_float2(v2, v3);
            }
        }
    }
}

// ---------------------------------------------------------------------------
// MLP GEMM via mma.sync — unchanged from R9 (proven)
// ---------------------------------------------------------------------------
#define MLP_SA_LO (128 * RSTR)

template<int MODE>
__global__ __launch_bounds__(256) void mlp_gemm(
    const int* __restrict__ c0, const int* __restrict__ c1,
    const int* __restrict__ c2, const float* __restrict__ bias)
{
    constexpr int CIN  = (MODE == 1) ? 64 : 256;
    constexpr int COUT = (MODE == 3) ? 64 : 256;
    constexpr int CTAN = (COUT >= 256) ? 128 : 64;
    constexpr int NT   = CTAN / 16;
    constexpr int SB_HI = 2 * 128 * RSTR;
    constexpr int SB_LO = SB_HI + CTAN * RSTR;

    extern __shared__ char smem[];
    const int tid = threadIdx.x;
    const int warp = tid >> 5, lane = tid & 31;
    const int wm = warp >> 1, wn = warp & 1;
    const int g = lane >> 2, tg = lane & 3;
    const int p0 = blockIdx.x * 128;
    const int n0 = blockIdx.y * CTAN;

    const int m = tid >> 1, half = tid & 1;
    const int row = p0 + m;

    float acc[2][NT][4];
    #pragma unroll
    for (int mt = 0; mt < 2; mt++)
        #pragma unroll
        for (int nt = 0; nt < NT; nt++)
            #pragma unroll
            for (int q = 0; q < 4; q++) acc[mt][nt][q] = 0.f;

    for (int cb = 0; cb < CIN; cb += 64) {
        __syncthreads();
        if (MODE == 1) {
            bool ok = row < NPTS;
            const float4* src = nullptr;
            if (ok) {
                int v = c0[row] * DD + c1[row] * DIM + c2[row];
                src = (const float4*)(g_f2 + (size_t)v * 64 + half * 32);
            }
            u32 hw[16], lw[16];
            #pragma unroll
            for (int i = 0; i < 8; i++) {
                float4 q = ok ? src[i] : make_float4(0.f, 0.f, 0.f, 0.f);
                __nv_bfloat16 ah = __float2bfloat16_rn(q.x);
                __nv_bfloat16 al = __float2bfloat16_rn(q.x - __bfloat162float(ah));
                __nv_bfloat16 bh = __float2bfloat16_rn(q.y);
                __nv_bfloat16 bl = __float2bfloat16_rn(q.y - __bfloat162float(bh));
                hw[2*i]   = pkbf(ah, bh);
                lw[2*i]   = pkbf(al, bl);
                ah = __float2bfloat16_rn(q.z);
                al = __float2bfloat16_rn(q.z - __bfloat162float(ah));
                bh = __float2bfloat16_rn(q.w);
                bl = __float2bfloat16_rn(q.w - __bfloat162float(bh));
                hw[2*i+1] = pkbf(ah, bh);
                lw[2*i+1] = pkbf(al, bl);
            }
            #pragma unroll
            for (int i = 0; i < 4; i++) {
                u32 off = m * RSTR + half * 64 + i * 16;
                *(uint4*)(smem + 0 + off) =
                    make_uint4(hw[4*i], hw[4*i+1], hw[4*i+2], hw[4*i+3]);
                *(uint4*)(smem + MLP_SA_LO + off) =
                    make_uint4(lw[4*i], lw[4*i+1], lw[4*i+2], lw[4*i+3]);
            }
        } else {
            const __nv_bfloat16* Ahi = (MODE == 2) ? g_h1hi : g_h2hi;
            const __nv_bfloat16* Alo = (MODE == 2) ? g_h1lo : g_h2lo;
            const uint4* shi = (const uint4*)(Ahi + (size_t)row * CIN + cb + half * 32);
            const uint4* slo = (const uint4*)(Alo + (size_t)row * CIN + cb + half * 32);
            #pragma unroll
            for (int i = 0; i < 4; i++) {
                u32 off = m * RSTR + half * 64 + i * 16;
                *(uint4*)(smem + 0 + off) = shi[i];
                *(uint4*)(smem + MLP_SA_LO + off) = slo[i];
            }
        }
        {
            const __nv_bfloat16* Whi =
                (MODE == 1) ? g_mw1hi : (MODE == 2) ? g_mw2hi : g_mw3hi;
            const __nv_bfloat16* Wlo =
                (MODE == 1) ? g_mw1lo : (MODE == 2) ? g_mw2lo : g_mw3lo;
            for (int u = tid; u < CTAN * 2; u += 256) {
                int n = u >> 1, h = u & 1;
                const uint4* sh =
                    (const uint4*)(Whi + (size_t)(n0 + n) * CIN + cb + h * 32);
                const uint4* sl =
                    (const uint4*)(Wlo + (size_t)(n0 + n) * CIN + cb + h * 32);
                #pragma unroll
                for (int i = 0; i < 4; i++) {
                    u32 off = n * RSTR + h * 64 + i * 16;
                    *(uint4*)(smem + SB_HI + off) = sh[i];
                    *(uint4*)(smem + SB_LO + off) = sl[i];
                }
            }
        }
        __syncthreads();

        #pragma unroll
        for (int ks = 0; ks < 4; ks++) {
            u32 ah[2][4], al[2][4];
            #pragma unroll
            for (int mt = 0; mt < 2; mt++) {
                u32 base = (wm * 32 + mt * 16 + g) * RSTR + ks * 32 + tg * 4;
                ah[mt][0] = *(const u32*)(smem + 0 + base);
                ah[mt][1] = *(const u32*)(smem + 0 + base + 8 * RSTR);
                ah[mt][2] = *(const u32*)(smem + 0 + base + 16);
                ah[mt][3] = *(const u32*)(smem + 0 + base + 8 * RSTR + 16);
                al[mt][0] = *(const u32*)(smem + MLP_SA_LO + base);
                al[mt][1] = *(const u32*)(smem + MLP_SA_LO + base + 8 * RSTR);
                al[mt][2] = *(const u32*)(smem + MLP_SA_LO + base + 16);
                al[mt][3] = *(const u32*)(smem + MLP_SA_LO + base + 8 * RSTR + 16);
            }
            u32 bh[NT][2], bl[NT][2];
            #pragma unroll
            for (int nt = 0; nt < NT; nt++) {
                u32 base = (wn * (CTAN / 2) + nt * 8 + g) * RSTR + ks * 32 + tg * 4;
                bh[nt][0] = *(const u32*)(smem + SB_HI + base);
                bh[nt][1] = *(const u32*)(smem + SB_HI + base + 16);
                bl[nt][0] = *(const u32*)(smem + SB_LO + base);
                bl[nt][1] = *(const u32*)(smem + SB_LO + base + 16);
            }
            #pragma unroll
            for (int mt = 0; mt < 2; mt++)
                #pragma unroll
                for (int nt = 0; nt < NT; nt++) {
                    mma16816(acc[mt][nt], ah[mt], bh[nt]);
                    mma16816(acc[mt][nt], ah[mt], bl[nt]);
                    mma16816(acc[mt][nt], al[mt], bh[nt]);
                }
        }
    }

    #pragma unroll
    for (int mt = 0; mt < 2; mt++) {
        #pragma unroll
        for (int nt = 0; nt < NT; nt++) {
            const int nl = wn * (CTAN / 2) + nt * 8 + tg * 2;
            const int gc = n0 + nl;
            const float b0 = __ldg(bias + gc), b1 = __ldg(bias + gc + 1);
            const int pixA = p0 + wm * 32 + mt * 16 + g;
            const int pixB = pixA + 8;
            float v0 = acc[mt][nt][0] + b0;
            float v1 = acc[mt][nt][1] + b1;
            float v2 = acc[mt][nt][2] + b0;
            float v3 = acc[mt][nt][3] + b1;
            if (MODE != 3) {
                v0 = fmaxf(v0, 0.f); v1 = fmaxf(v1, 0.f);
                v2 = fmaxf(v2, 0.f); v3 = fmaxf(v3, 0.f);
                __nv_bfloat16* Ohi = (MODE == 1) ? g_h1hi : g_h2hi;
                __nv_bfloat16* Olo = (MODE == 1) ? g_h1lo : g_h2lo;
                __nv_bfloat16 h0 = __float2bfloat16_rn(v0);
                __nv_bfloat16 h1 = __float2bfloat16_rn(v1);
                __nv_bfloat16 h2 = __float2bfloat16_rn(v2);
                __nv_bfloat16 h3 = __float2bfloat16_rn(v3);
                *(u32*)(Ohi + (size_t)pixA * 256 + gc) = pkbf(h0, h1);
                *(u32*)(Ohi + (size_t)pixB * 256 + gc) = pkbf(h2, h3);
                *(u32*)(Olo + (size_t)pixA * 256 + gc) =
                    pkbf(__float2bfloat16_rn(v0 - __bfloat162float(h0)),
                         __float2bfloat16_rn(v1 - __bfloat162float(h1)));
                *(u32*)(Olo + (size_t)pixB * 256 + gc) =
                    pkbf(__float2bfloat16_rn(v2 - __bfloat162float(h2)),
                         __float2bfloat16_rn(v3 - __bfloat162float(h3)));
            } else {
                *(float2*)(g_h3 + (size_t)pixA * 64 + gc) = make_float2(v0, v1);
                *(float2*)(g_h3 + (size_t)pixB * 64 + gc) = make_float2(v2, v3);
            }
        }
    }
}

// ---------------------------------------------------------------------------
// Final layer: out[o][p] = b4[o] + sum_c w4[o][c] * h3[p][c]
// ---------------------------------------------------------------------------
__global__ __launch_bounds__(256) void mlp_l4(
    const float* __restrict__ w4, const float* __restrict__ b4,
    float* __restrict__ out)
{
    __shared__ float ws[384];
    __shared__ float bs[6];
    int tid = threadIdx.x;
    for (int i = tid; i < 384; i += 256) ws[i] = w4[i];
    if (tid < 6) bs[tid] = b4[tid];
    __syncthreads();
    int p = blockIdx.x * 256 + tid;
    if (p >= NPTS) return;
    float h[64];
    const float4* src = (const float4*)(g_h3 + (size_t)p * 64);
    #pragma unroll
    for (int i = 0; i < 16; i++) {
        float4 q = src[i];
        h[4*i] = q.x; h[4*i+1] = q.y; h[4*i+2] = q.z; h[4*i+3] = q.w;
    }
    #pragma unroll
    for (int o = 0; o < 6; o++) {
        float a = bs[o];
        #pragma unroll
        for (int c = 0; c < 64; c++)
            a = fmaf(ws[o * 64 + c], h[c], a);
        out[(size_t)o * NPTS + p] = a;
    }
}

// ---------------------------------------------------------------------------
extern "C" void kernel_launch(void* const* d_in, const int* in_sizes, int n_in,
                              void* d_out, int out_size)
{
    const float* img = (const float*)d_in[0];
    const int*   c0  = (const int*)d_in[1];
    const int*   c1  = (const int*)d_in[2];
    const int*   c2  = (const int*)d_in[3];
    const float* we1 = (const float*)d_in[4];
    const float* be1 = (const float*)d_in[5];
    const float* we2 = (const float*)d_in[6];
    const float* be2 = (const float*)d_in[7];
    const float* wp1 = (const float*)d_in[8];
    const float* bp1 = (const float*)d_in[9];
    const float* wp2 = (const float*)d_in[10];
    const float* bp2 = (const float*)d_in[11];
    const float* wp3 = (const float*)d_in[12];
    const float* bp3 = (const float*)d_in[13];
    const float* wp4 = (const float*)d_in[14];
    const float* bp4 = (const float*)d_in[15];
    float* out = (float*)d_out;

    cudaFuncSetAttribute(conv_mma<1>,
                         cudaFuncAttributeMaxDynamicSharedMemorySize, SMEM_CONV);
    cudaFuncSetAttribute(conv_mma<2>,
                         cudaFuncAttributeMaxDynamicSharedMemorySize, SMEM_CONV);
    const int smemG1 = 2 * 128 * RSTR + 2 * 128 * RSTR;   // 73728
    const int smemG3 = 2 * 128 * RSTR + 2 * 64 * RSTR;    // 55296
    cudaFuncSetAttribute(mlp_gemm<1>,
                         cudaFuncAttributeMaxDynamicSharedMemorySize, smemG1);
    cudaFuncSetAttribute(mlp_gemm<2>,
                         cudaFuncAttributeMaxDynamicSharedMemorySize, smemG1);
    cudaFuncSetAttribute(mlp_gemm<3>,
                         cudaFuncAttributeMaxDynamicSharedMemorySize, smemG3);

    __nv_bfloat16 *mw1hi, *mw1lo, *mw2hi, *mw2lo, *mw3hi, *mw3lo;
    cudaGetSymbolAddress((void**)&mw1hi, g_mw1hi);
    cudaGetSymbolAddress((void**)&mw1lo, g_mw1lo);
    cudaGetSymbolAddress((void**)&mw2hi, g_mw2hi);
    cudaGetSymbolAddress((void**)&mw2lo, g_mw2lo);
    cudaGetSymbolAddress((void**)&mw3hi, g_mw3hi);
    cudaGetSymbolAddress((void**)&mw3lo, g_mw3lo);

    prep_img<<<2000, 256>>>(img);
    prep_w1<<<(14 * 4096 + 255) / 256, 256>>>(we1);
    prep_w2<<<(27 * 4096 + 255) / 256, 256>>>(we2);
    prep_wmlp<<<(256 * 64 + 255) / 256, 256>>>(wp1, mw1hi, mw1lo, 256 * 64);
    prep_wmlp<<<(256 * 256 + 255) / 256, 256>>>(wp2, mw2hi, mw2lo, 256 * 256);
    prep_wmlp<<<(64 * 256 + 255) / 256, 256>>>(wp3, mw3hi, mw3lo, 64 * 256);

    conv_mma<1><<<D3 / CTAM, 256, SMEM_CONV>>>(be1);
    conv_mma<2><<<D3 / CTAM, 256, SMEM_CONV>>>(be2);

    dim3 g12(NPAD / 128, 2);
    mlp_gemm<1><<<g12, 256, smemG1>>>(c0, c1, c2, bp1);
    mlp_gemm<2><<<g12, 256, smemG1>>>(c0, c1, c2, bp2);
    dim3 g3(NPAD / 128, 1);
    mlp_gemm<3><<<g3, 256, smemG3>>>(c0, c1, c2, bp3);
    mlp_l4<<<(NPTS + 255) / 256, 256>>>(wp4, bp4, out);
}

// round 11
// speedup vs baseline: 1.1304x; 1.1304x over previous
#include <cuda_runtime.h>
#include <cuda_bf16.h>
#include <cstdint>

#define DIM 80
#define DD 6400
#define D3 512000
#define NPTS 200000
#define NPAD 200064   // 1563 * 128

typedef unsigned long long u64;
typedef unsigned int u32;

// ---------------------------------------------------------------------------
// Device scratch (no allocations in kernel_launch)
// ---------------------------------------------------------------------------
__device__ __nv_bfloat16 g_xhi[D3 * 32];
__device__ __nv_bfloat16 g_xlo[D3 * 32];
__device__ __nv_bfloat16 g_f1hi[D3 * 64];
__device__ __nv_bfloat16 g_f1lo[D3 * 64];
__device__ float         g_f2[D3 * 64];
__device__ __nv_bfloat16 g_w1hi[14 * 64 * 64], g_w1lo[14 * 64 * 64];
__device__ __nv_bfloat16 g_w2hi[27 * 64 * 64], g_w2lo[27 * 64 * 64];
// MLP
__device__ __nv_bfloat16 g_h1hi[(size_t)NPAD * 256], g_h1lo[(size_t)NPAD * 256];
__device__ __nv_bfloat16 g_h2hi[(size_t)NPAD * 256], g_h2lo[(size_t)NPAD * 256];
__device__ float         g_h3[(size_t)NPAD * 64];
__device__ __nv_bfloat16 g_mw1hi[256 * 64],  g_mw1lo[256 * 64];
__device__ __nv_bfloat16 g_mw2hi[256 * 256], g_mw2lo[256 * 256];
__device__ __nv_bfloat16 g_mw3hi[64 * 256],  g_mw3lo[64 * 256];

__device__ __forceinline__ u32 pkbf(__nv_bfloat16 a, __nv_bfloat16 b) {
    return (u32)__bfloat16_as_ushort(a) | ((u32)__bfloat16_as_ushort(b) << 16);
}

__device__ __forceinline__ void mma16816(float* d, const u32* a, const u32* b) {
    asm volatile(
        "mma.sync.aligned.m16n8k16.row.col.f32.bf16.bf16.f32 "
        "{%0,%1,%2,%3}, {%4,%5,%6,%7}, {%8,%9}, {%0,%1,%2,%3};"
        : "+f"(d[0]), "+f"(d[1]), "+f"(d[2]), "+f"(d[3])
        : "r"(a[0]), "r"(a[1]), "r"(a[2]), "r"(a[3]), "r"(b[0]), "r"(b[1]));
}

// cp.async 16B with zero-fill predication (src_bytes = 0 -> zeros)
__device__ __forceinline__ void cpasync16(u32 dst, const void* src, int nbytes) {
    asm volatile("cp.async.cg.shared.global [%0], [%1], 16, %2;"
                 :: "r"(dst), "l"(src), "r"(nbytes));
}
#define CP_COMMIT() asm volatile("cp.async.commit_group;" ::: "memory")

// ---------------------------------------------------------------------------
// Prep kernels
// ---------------------------------------------------------------------------
__global__ void prep_img(const float* __restrict__ img) {
    int p = blockIdx.x * 256 + threadIdx.x;
    u32 hw[16], lw[16];
    #pragma unroll
    for (int c = 0; c < 32; c += 2) {
        float a = img[c * D3 + p];
        float b = img[(c + 1) * D3 + p];
        __nv_bfloat16 ah = __float2bfloat16_rn(a);
        __nv_bfloat16 al = __float2bfloat16_rn(a - __bfloat162float(ah));
        __nv_bfloat16 bh = __float2bfloat16_rn(b);
        __nv_bfloat16 bl = __float2bfloat16_rn(b - __bfloat162float(bh));
        hw[c >> 1] = pkbf(ah, bh);
        lw[c >> 1] = pkbf(al, bl);
    }
    uint4* oh = (uint4*)(g_xhi + (size_t)p * 32);
    uint4* ol = (uint4*)(g_xlo + (size_t)p * 32);
    #pragma unroll
    for (int q = 0; q < 4; q++) {
        oh[q] = make_uint4(hw[q*4], hw[q*4+1], hw[q*4+2], hw[q*4+3]);
        ol[q] = make_uint4(lw[q*4], lw[q*4+1], lw[q*4+2], lw[q*4+3]);
    }
}

__global__ void prep_w1(const float* __restrict__ w) {
    int idx = blockIdx.x * 256 + threadIdx.x;
    if (idx >= 14 * 4096) return;
    int j = idx >> 12, r = idx & 4095, o = r >> 6, k = r & 63;
    int t = k >> 5, c = k & 31, tp = 2 * j + t;
    float v = (tp <= 26) ? w[(o * 32 + c) * 27 + tp] : 0.f;
    __nv_bfloat16 h = __float2bfloat16_rn(v);
    g_w1hi[idx] = h;
    g_w1lo[idx] = __float2bfloat16_rn(v - __bfloat162float(h));
}
__global__ void prep_w2(const float* __restrict__ w) {
    int idx = blockIdx.x * 256 + threadIdx.x;
    if (idx >= 27 * 4096) return;
    int j = idx >> 12, r = idx & 4095, o = r >> 6, c = r & 63;
    float v = w[(o * 64 + c) * 27 + j];
    __nv_bfloat16 h = __float2bfloat16_rn(v);
    g_w2hi[idx] = h;
    g_w2lo[idx] = __float2bfloat16_rn(v - __bfloat162float(h));
}

__global__ void prep_wmlp(const float* __restrict__ src,
                          __nv_bfloat16* __restrict__ dhi,
                          __nv_bfloat16* __restrict__ dlo, int n) {
    int i = blockIdx.x * 256 + threadIdx.x;
    if (i >= n) return;
    float v = src[i];
    __nv_bfloat16 h = __float2bfloat16_rn(v);
    dhi[i] = h;
    dlo[i] = __float2bfloat16_rn(v - __bfloat162float(h));
}

// ---------------------------------------------------------------------------
// Conv via mma.sync — R9 geometry (CTA 128 px x 64 oc, warp tile 32x32),
// R11: double-buffered smem + cp.async pipeline (stage tap j+1 during
// compute of tap j). Buffer = 55296 B; two buffers = 110592 B, 2 CTAs/SM.
// ---------------------------------------------------------------------------
#define RSTR 144
#define SA_HI 0
#define SA_LO (128 * RSTR)
#define SW_HI (2 * 128 * RSTR)
#define SW_LO (2 * 128 * RSTR + 64 * RSTR)
#define CBUF  (2 * 128 * RSTR + 2 * 64 * RSTR)   // 55296
#define SMEM_CONV (2 * CBUF)                      // 110592

template<int STAGE>
__device__ __forceinline__ void conv_stage(
    int j, u32 sbuf,
    const __nv_bfloat16* __restrict__ Xhi, const __nv_bfloat16* __restrict__ Xlo,
    const __nv_bfloat16* __restrict__ Whi, const __nv_bfloat16* __restrict__ Wlo,
    int tid, int m, int half, int p, int z, int y, int x)
{
    // ---- A rows ----
    if (STAGE == 1) {
        int tp = 2 * j + half;
        int kz = tp / 9, ky = (tp / 3) % 3, kx = tp % 3;
        bool v = (tp <= 26) &&
                 (unsigned)(z + kz - 1) < 80u &&
                 (unsigned)(y + ky - 1) < 80u &&
                 (unsigned)(x + kx - 1) < 80u;
        int ps = p + (kz - 1) * DD + (ky - 1) * DIM + (kx - 1);
        const uint4* shi = (const uint4*)(Xhi + (size_t)ps * 32);
        const uint4* slo = (const uint4*)(Xlo + (size_t)ps * 32);
        int n16 = v ? 16 : 0;
        #pragma unroll
        for (int i = 0; i < 4; i++) {
            u32 off = m * RSTR + half * 64 + i * 16;
            cpasync16(sbuf + SA_HI + off, shi + i, n16);
            cpasync16(sbuf + SA_LO + off, slo + i, n16);
        }
    } else {
        int kz = j / 9, ky = (j / 3) % 3, kx = j % 3;
        bool v = (unsigned)(z + kz - 1) < 80u &&
                 (unsigned)(y + ky - 1) < 80u &&
                 (unsigned)(x + kx - 1) < 80u;
        int ps = p + (kz - 1) * DD + (ky - 1) * DIM + (kx - 1);
        const uint4* shi = (const uint4*)(Xhi + (size_t)ps * 64) + half * 4;
        const uint4* slo = (const uint4*)(Xlo + (size_t)ps * 64) + half * 4;
        int n16 = v ? 16 : 0;
        #pragma unroll
        for (int i = 0; i < 4; i++) {
            u32 off = m * RSTR + half * 64 + i * 16;
            cpasync16(sbuf + SA_HI + off, shi + i, n16);
            cpasync16(sbuf + SA_LO + off, slo + i, n16);
        }
    }
    // ---- W rows ----
    {
        const uint4* wh = (const uint4*)(Whi + j * 4096);
        const uint4* wl = (const uint4*)(Wlo + j * 4096);
        #pragma unroll
        for (int u = tid; u < 512; u += 256) {
            u32 off = (u >> 3) * RSTR + (u & 7) * 16;
            cpasync16(sbuf + SW_HI + off, wh + u, 16);
            cpasync16(sbuf + SW_LO + off, wl + u, 16);
        }
    }
}

template<int STAGE>
__global__ __launch_bounds__(256) void conv_mma(const float* __restrict__ bias)
{
    constexpr int NCH = (STAGE == 1) ? 14 : 27;
    const __nv_bfloat16* Xhi = (STAGE == 1) ? g_xhi : g_f1hi;
    const __nv_bfloat16* Xlo = (STAGE == 1) ? g_xlo : g_f1lo;
    const __nv_bfloat16* Whi = (STAGE == 1) ? g_w1hi : g_w2hi;
    const __nv_bfloat16* Wlo = (STAGE == 1) ? g_w1lo : g_w2lo;

    extern __shared__ char smem[];
    const u32 sb = (u32)__cvta_generic_to_shared(smem);
    const int tid = threadIdx.x;
    const int warp = tid >> 5, lane = tid & 31;
    const int p0 = blockIdx.x * 128;

    const int m = tid >> 1, half = tid & 1;
    const int p = p0 + m;
    const int z = p / DD;
    const int rr = p - z * DD;
    const int y = rr / DIM;
    const int x = rr - y * DIM;

    const int wm = warp >> 1, wn = warp & 1;
    const int g = lane >> 2, tg = lane & 3;

    float acc[2][4][4];
    #pragma unroll
    for (int mt = 0; mt < 2; mt++)
        #pragma unroll
        for (int nt = 0; nt < 4; nt++)
            #pragma unroll
            for (int q = 0; q < 4; q++) acc[mt][nt][q] = 0.f;

    // prologue: stage tap 0 into buffer 0
    conv_stage<STAGE>(0, sb, Xhi, Xlo, Whi, Wlo, tid, m, half, p, z, y, x);
    CP_COMMIT();

    for (int j = 0; j < NCH; j++) {
        const int buf = j & 1;
        if (j + 1 < NCH) {
            conv_stage<STAGE>(j + 1, sb + (buf ^ 1) * CBUF,
                              Xhi, Xlo, Whi, Wlo, tid, m, half, p, z, y, x);
            CP_COMMIT();
            asm volatile("cp.async.wait_group 1;" ::: "memory");
        } else {
            asm volatile("cp.async.wait_group 0;" ::: "memory");
        }
        __syncthreads();

        const char* bp = smem + buf * CBUF;
        #pragma unroll
        for (int ks = 0; ks < 4; ks++) {
            u32 ah[2][4], al[2][4];
            #pragma unroll
            for (int mt = 0; mt < 2; mt++) {
                u32 base = (wm * 32 + mt * 16 + g) * RSTR + ks * 32 + tg * 4;
                ah[mt][0] = *(const u32*)(bp + SA_HI + base);
                ah[mt][1] = *(const u32*)(bp + SA_HI + base + 8 * RSTR);
                ah[mt][2] = *(const u32*)(bp + SA_HI + base + 16);
                ah[mt][3] = *(const u32*)(bp + SA_HI + base + 8 * RSTR + 16);
                al[mt][0] = *(const u32*)(bp + SA_LO + base);
                al[mt][1] = *(const u32*)(bp + SA_LO + base + 8 * RSTR);
                al[mt][2] = *(const u32*)(bp + SA_LO + base + 16);
                al[mt][3] = *(const u32*)(bp + SA_LO + base + 8 * RSTR + 16);
            }
            u32 bh[4][2], bl[4][2];
            #pragma unroll
            for (int nt = 0; nt < 4; nt++) {
                u32 base = (wn * 32 + nt * 8 + g) * RSTR + ks * 32 + tg * 4;
                bh[nt][0] = *(const u32*)(bp + SW_HI + base);
                bh[nt][1] = *(const u32*)(bp + SW_HI + base + 16);
                bl[nt][0] = *(const u32*)(bp + SW_LO + base);
                bl[nt][1] = *(const u32*)(bp + SW_LO + base + 16);
            }
            #pragma unroll
            for (int mt = 0; mt < 2; mt++)
                #pragma unroll
                for (int nt = 0; nt < 4; nt++) {
                    mma16816(acc[mt][nt], ah[mt], bh[nt]);
                    mma16816(acc[mt][nt], ah[mt], bl[nt]);
                    mma16816(acc[mt][nt], al[mt], bh[nt]);
                }
        }
        __syncthreads();
    }

    #pragma unroll
    for (int mt = 0; mt < 2; mt++) {
        #pragma unroll
        for (int nt = 0; nt < 4; nt++) {
            const int n = wn * 32 + nt * 8 + tg * 2;
            const float b0 = __ldg(bias + n), b1 = __ldg(bias + n + 1);
            const int pixA = p0 + wm * 32 + mt * 16 + g;
            const int pixB = pixA + 8;
            float v0 = fmaxf(acc[mt][nt][0] + b0, 0.f);
            float v1 = fmaxf(acc[mt][nt][1] + b1, 0.f);
            float v2 = fmaxf(acc[mt][nt][2] + b0, 0.f);
            float v3 = fmaxf(acc[mt][nt][3] + b1, 0.f);
            if (STAGE == 1) {
                __nv_bfloat16 h0 = __float2bfloat16_rn(v0);
                __nv_bfloat16 h1 = __float2bfloat16_rn(v1);
                __nv_bfloat16 h2 = __float2bfloat16_rn(v2);
                __nv_bfloat16 h3 = __float2bfloat16_rn(v3);
                *(u32*)(g_f1hi + (size_t)pixA * 64 + n) = pkbf(h0, h1);
                *(u32*)(g_f1hi + (size_t)pixB * 64 + n) = pkbf(h2, h3);
                *(u32*)(g_f1lo + (size_t)pixA * 64 + n) =
                    pkbf(__float2bfloat16_rn(v0 - __bfloat162float(h0)),
                         __float2bfloat16_rn(v1 - __bfloat162float(h1)));
                *(u32*)(g_f1lo + (size_t)pixB * 64 + n) =
                    pkbf(__float2bfloat16_rn(v2 - __bfloat162float(h2)),
                         __float2bfloat16_rn(v3 - __bfloat162float(h3)));
            } else {
                *(float2*)(g_f2 + (size_t)pixA * 64 + n) = make_float2(v0, v1);
                *(float2*)(g_f2 + (size_t)pixB * 64 + n) = make_float2(v2, v3);
            }
        }
    }
}

// ---------------------------------------------------------------------------
// MLP GEMM via mma.sync — unchanged from R9 (proven)
// ---------------------------------------------------------------------------
#define MLP_SA_LO (128 * RSTR)

template<int MODE>
__global__ __launch_bounds__(256) void mlp_gemm(
    const int* __restrict__ c0, const int* __restrict__ c1,
    const int* __restrict__ c2, const float* __restrict__ bias)
{
    constexpr int CIN  = (MODE == 1) ? 64 : 256;
    constexpr int COUT = (MODE == 3) ? 64 : 256;
    constexpr int CTAN = (COUT >= 256) ? 128 : 64;
    constexpr int NT   = CTAN / 16;
    constexpr int SB_HI = 2 * 128 * RSTR;
    constexpr int SB_LO = SB_HI + CTAN * RSTR;

    extern __shared__ char smem[];
    const int tid = threadIdx.x;
    const int warp = tid >> 5, lane = tid & 31;
    const int wm = warp >> 1, wn = warp & 1;
    const int g = lane >> 2, tg = lane & 3;
    const int p0 = blockIdx.x * 128;
    const int n0 = blockIdx.y * CTAN;

    const int m = tid >> 1, half = tid & 1;
    const int row = p0 + m;

    float acc[2][NT][4];
    #pragma unroll
    for (int mt = 0; mt < 2; mt++)
        #pragma unroll
        for (int nt = 0; nt < NT; nt++)
            #pragma unroll
            for (int q = 0; q < 4; q++) acc[mt][nt][q] = 0.f;

    for (int cb = 0; cb < CIN; cb += 64) {
        __syncthreads();
        if (MODE == 1) {
            bool ok = row < NPTS;
            const float4* src = nullptr;
            if (ok) {
                int v = c0[row] * DD + c1[row] * DIM + c2[row];
                src = (const float4*)(g_f2 + (size_t)v * 64 + half * 32);
            }
            u32 hw[16], lw[16];
            #pragma unroll
            for (int i = 0; i < 8; i++) {
                float4 q = ok ? src[i] : make_float4(0.f, 0.f, 0.f, 0.f);
                __nv_bfloat16 ah = __float2bfloat16_rn(q.x);
                __nv_bfloat16 al = __float2bfloat16_rn(q.x - __bfloat162float(ah));
                __nv_bfloat16 bh = __float2bfloat16_rn(q.y);
                __nv_bfloat16 bl = __float2bfloat16_rn(q.y - __bfloat162float(bh));
                hw[2*i]   = pkbf(ah, bh);
                lw[2*i]   = pkbf(al, bl);
                ah = __float2bfloat16_rn(q.z);
                al = __float2bfloat16_rn(q.z - __bfloat162float(ah));
                bh = __float2bfloat16_rn(q.w);
                bl = __float2bfloat16_rn(q.w - __bfloat162float(bh));
                hw[2*i+1] = pkbf(ah, bh);
                lw[2*i+1] = pkbf(al, bl);
            }
            #pragma unroll
            for (int i = 0; i < 4; i++) {
                u32 off = m * RSTR + half * 64 + i * 16;
                *(uint4*)(smem + 0 + off) =
                    make_uint4(hw[4*i], hw[4*i+1], hw[4*i+2], hw[4*i+3]);
                *(uint4*)(smem + MLP_SA_LO + off) =
                    make_uint4(lw[4*i], lw[4*i+1], lw[4*i+2], lw[4*i+3]);
            }
        } else {
            const __nv_bfloat16* Ahi = (MODE == 2) ? g_h1hi : g_h2hi;
            const __nv_bfloat16* Alo = (MODE == 2) ? g_h1lo : g_h2lo;
            const uint4* shi = (const uint4*)(Ahi + (size_t)row * CIN + cb + half * 32);
            const uint4* slo = (const uint4*)(Alo + (size_t)row * CIN + cb + half * 32);
            #pragma unroll
            for (int i = 0; i < 4; i++) {
                u32 off = m * RSTR + half * 64 + i * 16;
                *(uint4*)(smem + 0 + off) = shi[i];
                *(uint4*)(smem + MLP_SA_LO + off) = slo[i];
            }
        }
        {
            const __nv_bfloat16* Whi =
                (MODE == 1) ? g_mw1hi : (MODE == 2) ? g_mw2hi : g_mw3hi;
            const __nv_bfloat16* Wlo =
                (MODE == 1) ? g_mw1lo : (MODE == 2) ? g_mw2lo : g_mw3lo;
            for (int u = tid; u < CTAN * 2; u += 256) {
                int n = u >> 1, h = u & 1;
                const uint4* sh =
                    (const uint4*)(Whi + (size_t)(n0 + n) * CIN + cb + h * 32);
                const uint4* sl =
                    (const uint4*)(Wlo + (size_t)(n0 + n) * CIN + cb + h * 32);
                #pragma unroll
                for (int i = 0; i < 4; i++) {
                    u32 off = n * RSTR + h * 64 + i * 16;
                    *(uint4*)(smem + SB_HI + off) = sh[i];
                    *(uint4*)(smem + SB_LO + off) = sl[i];
                }
            }
        }
        __syncthreads();

        #pragma unroll
        for (int ks = 0; ks < 4; ks++) {
            u32 ah[2][4], al[2][4];
            #pragma unroll
            for (int mt = 0; mt < 2; mt++) {
                u32 base = (wm * 32 + mt * 16 + g) * RSTR + ks * 32 + tg * 4;
                ah[mt][0] = *(const u32*)(smem + 0 + base);
                ah[mt][1] = *(const u32*)(smem + 0 + base + 8 * RSTR);
                ah[mt][2] = *(const u32*)(smem + 0 + base + 16);
                ah[mt][3] = *(const u32*)(smem + 0 + base + 8 * RSTR + 16);
                al[mt][0] = *(const u32*)(smem + MLP_SA_LO + base);
                al[mt][1] = *(const u32*)(smem + MLP_SA_LO + base + 8 * RSTR);
                al[mt][2] = *(const u32*)(smem + MLP_SA_LO + base + 16);
                al[mt][3] = *(const u32*)(smem + MLP_SA_LO + base + 8 * RSTR + 16);
            }
            u32 bh[NT][2], bl[NT][2];
            #pragma unroll
            for (int nt = 0; nt < NT; nt++) {
                u32 base = (wn * (CTAN / 2) + nt * 8 + g) * RSTR + ks * 32 + tg * 4;
                bh[nt][0] = *(const u32*)(smem + SB_HI + base);
                bh[nt][1] = *(const u32*)(smem + SB_HI + base + 16);
                bl[nt][0] = *(const u32*)(smem + SB_LO + base);
                bl[nt][1] = *(const u32*)(smem + SB_LO + base + 16);
            }
            #pragma unroll
            for (int mt = 0; mt < 2; mt++)
                #pragma unroll
                for (int nt = 0; nt < NT; nt++) {
                    mma16816(acc[mt][nt], ah[mt], bh[nt]);
                    mma16816(acc[mt][nt], ah[mt], bl[nt]);
                    mma16816(acc[mt][nt], al[mt], bh[nt]);
                }
        }
    }

    #pragma unroll
    for (int mt = 0; mt < 2; mt++) {
        #pragma unroll
        for (int nt = 0; nt < NT; nt++) {
            const int nl = wn * (CTAN / 2) + nt * 8 + tg * 2;
            const int gc = n0 + nl;
            const float b0 = __ldg(bias + gc), b1 = __ldg(bias + gc + 1);
            const int pixA = p0 + wm * 32 + mt * 16 + g;
            const int pixB = pixA + 8;
            float v0 = acc[mt][nt][0] + b0;
            float v1 = acc[mt][nt][1] + b1;
            float v2 = acc[mt][nt][2] + b0;
            float v3 = acc[mt][nt][3] + b1;
            if (MODE != 3) {
                v0 = fmaxf(v0, 0.f); v1 = fmaxf(v1, 0.f);
                v2 = fmaxf(v2, 0.f); v3 = fmaxf(v3, 0.f);
                __nv_bfloat16* Ohi = (MODE == 1) ? g_h1hi : g_h2hi;
                __nv_bfloat16* Olo = (MODE == 1) ? g_h1lo : g_h2lo;
                __nv_bfloat16 h0 = __float2bfloat16_rn(v0);
                __nv_bfloat16 h1 = __float2bfloat16_rn(v1);
                __nv_bfloat16 h2 = __float2bfloat16_rn(v2);
                __nv_bfloat16 h3 = __float2bfloat16_rn(v3);
                *(u32*)(Ohi + (size_t)pixA * 256 + gc) = pkbf(h0, h1);
                *(u32*)(Ohi + (size_t)pixB * 256 + gc) = pkbf(h2, h3);
                *(u32*)(Olo + (size_t)pixA * 256 + gc) =
                    pkbf(__float2bfloat16_rn(v0 - __bfloat162float(h0)),
                         __float2bfloat16_rn(v1 - __bfloat162float(h1)));
                *(u32*)(Olo + (size_t)pixB * 256 + gc) =
                    pkbf(__float2bfloat16_rn(v2 - __bfloat162float(h2)),
                         __float2bfloat16_rn(v3 - __bfloat162float(h3)));
            } else {
                *(float2*)(g_h3 + (size_t)pixA * 64 + gc) = make_float2(v0, v1);
                *(float2*)(g_h3 + (size_t)pixB * 64 + gc) = make_float2(v2, v3);
            }
        }
    }
}

// ---------------------------------------------------------------------------
// Final layer: out[o][p] = b4[o] + sum_c w4[o][c] * h3[p][c]
// ---------------------------------------------------------------------------
__global__ __launch_bounds__(256) void mlp_l4(
    const float* __restrict__ w4, const float* __restrict__ b4,
    float* __restrict__ out)
{
    __shared__ float ws[384];
    __shared__ float bs[6];
    int tid = threadIdx.x;
    for (int i = tid; i < 384; i += 256) ws[i] = w4[i];
    if (tid < 6) bs[tid] = b4[tid];
    __syncthreads();
    int p = blockIdx.x * 256 + tid;
    if (p >= NPTS) return;
    float h[64];
    const float4* src = (const float4*)(g_h3 + (size_t)p * 64);
    #pragma unroll
    for (int i = 0; i < 16; i++) {
        float4 q = src[i];
        h[4*i] = q.x; h[4*i+1] = q.y; h[4*i+2] = q.z; h[4*i+3] = q.w;
    }
    #pragma unroll
    for (int o = 0; o < 6; o++) {
        float a = bs[o];
        #pragma unroll
        for (int c = 0; c < 64; c++)
            a = fmaf(ws[o * 64 + c], h[c], a);
        out[(size_t)o * NPTS + p] = a;
    }
}

// ---------------------------------------------------------------------------
extern "C" void kernel_launch(void* const* d_in, const int* in_sizes, int n_in,
                              void* d_out, int out_size)
{
    const float* img = (const float*)d_in[0];
    const int*   c0  = (const int*)d_in[1];
    const int*   c1  = (const int*)d_in[2];
    const int*   c2  = (const int*)d_in[3];
    const float* we1 = (const float*)d_in[4];
    const float* be1 = (const float*)d_in[5];
    const float* we2 = (const float*)d_in[6];
    const float* be2 = (const float*)d_in[7];
    const float* wp1 = (const float*)d_in[8];
    const float* bp1 = (const float*)d_in[9];
    const float* wp2 = (const float*)d_in[10];
    const float* bp2 = (const float*)d_in[11];
    const float* wp3 = (const float*)d_in[12];
    const float* bp3 = (const float*)d_in[13];
    const float* wp4 = (const float*)d_in[14];
    const float* bp4 = (const float*)d_in[15];
    float* out = (float*)d_out;

    cudaFuncSetAttribute(conv_mma<1>,
                         cudaFuncAttributeMaxDynamicSharedMemorySize, SMEM_CONV);
    cudaFuncSetAttribute(conv_mma<2>,
                         cudaFuncAttributeMaxDynamicSharedMemorySize, SMEM_CONV);
    const int smemG1 = 2 * 128 * RSTR + 2 * 128 * RSTR;   // 73728
    const int smemG3 = 2 * 128 * RSTR + 2 * 64 * RSTR;    // 55296
    cudaFuncSetAttribute(mlp_gemm<1>,
                         cudaFuncAttributeMaxDynamicSharedMemorySize, smemG1);
    cudaFuncSetAttribute(mlp_gemm<2>,
                         cudaFuncAttributeMaxDynamicSharedMemorySize, smemG1);
    cudaFuncSetAttribute(mlp_gemm<3>,
                         cudaFuncAttributeMaxDynamicSharedMemorySize, smemG3);

    __nv_bfloat16 *mw1hi, *mw1lo, *mw2hi, *mw2lo, *mw3hi, *mw3lo;
    cudaGetSymbolAddress((void**)&mw1hi, g_mw1hi);
    cudaGetSymbolAddress((void**)&mw1lo, g_mw1lo);
    cudaGetSymbolAddress((void**)&mw2hi, g_mw2hi);
    cudaGetSymbolAddress((void**)&mw2lo, g_mw2lo);
    cudaGetSymbolAddress((void**)&mw3hi, g_mw3hi);
    cudaGetSymbolAddress((void**)&mw3lo, g_mw3lo);

    prep_img<<<2000, 256>>>(img);
    prep_w1<<<(14 * 4096 + 255) / 256, 256>>>(we1);
    prep_w2<<<(27 * 4096 + 255) / 256, 256>>>(we2);
    prep_wmlp<<<(256 * 64 + 255) / 256, 256>>>(wp1, mw1hi, mw1lo, 256 * 64);
    prep_wmlp<<<(256 * 256 + 255) / 256, 256>>>(wp2, mw2hi, mw2lo, 256 * 256);
    prep_wmlp<<<(64 * 256 + 255) / 256, 256>>>(wp3, mw3hi, mw3lo, 64 * 256);

    conv_mma<1><<<4000, 256, SMEM_CONV>>>(be1);
    conv_mma<2><<<4000, 256, SMEM_CONV>>>(be2);

    dim3 g12(NPAD / 128, 2);
    mlp_gemm<1><<<g12, 256, smemG1>>>(c0, c1, c2, bp1);
    mlp_gemm<2><<<g12, 256, smemG1>>>(c0, c1, c2, bp2);
    dim3 g3(NPAD / 128, 1);
    mlp_gemm<3><<<g3, 256, smemG3>>>(c0, c1, c2, bp3);
    mlp_l4<<<(NPTS + 255) / 256, 256>>>(wp4, bp4, out);
}

// round 12
// speedup vs baseline: 1.3623x; 1.2051x over previous
#include <cuda_runtime.h>
#include <cuda_bf16.h>
#include <cstdint>

#define DIM 80
#define DD 6400
#define D3 512000
#define NPTS 200000
#define NPAD 200064   // 1563 * 128

typedef unsigned long long u64;
typedef unsigned int u32;

// ---------------------------------------------------------------------------
// Device scratch (no allocations in kernel_launch)
// ---------------------------------------------------------------------------
__device__ __nv_bfloat16 g_xhi[D3 * 32];
__device__ __nv_bfloat16 g_xlo[D3 * 32];
__device__ __nv_bfloat16 g_f1hi[D3 * 64];
__device__ __nv_bfloat16 g_f1lo[D3 * 64];
__device__ float         g_f2[D3 * 64];
__device__ __nv_bfloat16 g_w1hi[14 * 64 * 64], g_w1lo[14 * 64 * 64];
__device__ __nv_bfloat16 g_w2hi[27 * 64 * 64], g_w2lo[27 * 64 * 64];
// MLP
__device__ __nv_bfloat16 g_h1hi[(size_t)NPAD * 256], g_h1lo[(size_t)NPAD * 256];
__device__ __nv_bfloat16 g_h2hi[(size_t)NPAD * 256], g_h2lo[(size_t)NPAD * 256];
__device__ float         g_h3[(size_t)NPAD * 64];
__device__ __nv_bfloat16 g_mw1hi[256 * 64],  g_mw1lo[256 * 64];
__device__ __nv_bfloat16 g_mw2hi[256 * 256], g_mw2lo[256 * 256];
__device__ __nv_bfloat16 g_mw3hi[64 * 256],  g_mw3lo[64 * 256];

__device__ __forceinline__ u32 pkbf(__nv_bfloat16 a, __nv_bfloat16 b) {
    return (u32)__bfloat16_as_ushort(a) | ((u32)__bfloat16_as_ushort(b) << 16);
}

__device__ __forceinline__ void mma16816(float* d, const u32* a, const u32* b) {
    asm volatile(
        "mma.sync.aligned.m16n8k16.row.col.f32.bf16.bf16.f32 "
        "{%0,%1,%2,%3}, {%4,%5,%6,%7}, {%8,%9}, {%0,%1,%2,%3};"
        : "+f"(d[0]), "+f"(d[1]), "+f"(d[2]), "+f"(d[3])
        : "r"(a[0]), "r"(a[1]), "r"(a[2]), "r"(a[3]), "r"(b[0]), "r"(b[1]));
}

// ---------------------------------------------------------------------------
// Prep kernels
// ---------------------------------------------------------------------------
__global__ void prep_img(const float* __restrict__ img) {
    int p = blockIdx.x * 256 + threadIdx.x;
    u32 hw[16], lw[16];
    #pragma unroll
    for (int c = 0; c < 32; c += 2) {
        float a = img[c * D3 + p];
        float b = img[(c + 1) * D3 + p];
        __nv_bfloat16 ah = __float2bfloat16_rn(a);
        __nv_bfloat16 al = __float2bfloat16_rn(a - __bfloat162float(ah));
        __nv_bfloat16 bh = __float2bfloat16_rn(b);
        __nv_bfloat16 bl = __float2bfloat16_rn(b - __bfloat162float(bh));
        hw[c >> 1] = pkbf(ah, bh);
        lw[c >> 1] = pkbf(al, bl);
    }
    uint4* oh = (uint4*)(g_xhi + (size_t)p * 32);
    uint4* ol = (uint4*)(g_xlo + (size_t)p * 32);
    #pragma unroll
    for (int q = 0; q < 4; q++) {
        oh[q] = make_uint4(hw[q*4], hw[q*4+1], hw[q*4+2], hw[q*4+3]);
        ol[q] = make_uint4(lw[q*4], lw[q*4+1], lw[q*4+2], lw[q*4+3]);
    }
}

__global__ void prep_w1(const float* __restrict__ w) {
    int idx = blockIdx.x * 256 + threadIdx.x;
    if (idx >= 14 * 4096) return;
    int j = idx >> 12, r = idx & 4095, o = r >> 6, k = r & 63;
    int t = k >> 5, c = k & 31, tp = 2 * j + t;
    float v = (tp <= 26) ? w[(o * 32 + c) * 27 + tp] : 0.f;
    __nv_bfloat16 h = __float2bfloat16_rn(v);
    g_w1hi[idx] = h;
    g_w1lo[idx] = __float2bfloat16_rn(v - __bfloat162float(h));
}
__global__ void prep_w2(const float* __restrict__ w) {
    int idx = blockIdx.x * 256 + threadIdx.x;
    if (idx >= 27 * 4096) return;
    int j = idx >> 12, r = idx & 4095, o = r >> 6, c = r & 63;
    float v = w[(o * 64 + c) * 27 + j];
    __nv_bfloat16 h = __float2bfloat16_rn(v);
    g_w2hi[idx] = h;
    g_w2lo[idx] = __float2bfloat16_rn(v - __bfloat162float(h));
}

__global__ void prep_wmlp(const float* __restrict__ src,
                          __nv_bfloat16* __restrict__ dhi,
                          __nv_bfloat16* __restrict__ dlo, int n) {
    int i = blockIdx.x * 256 + threadIdx.x;
    if (i >= n) return;
    float v = src[i];
    __nv_bfloat16 h = __float2bfloat16_rn(v);
    dhi[i] = h;
    dlo[i] = __float2bfloat16_rn(v - __bfloat162float(h));
}

// ---------------------------------------------------------------------------
// Conv1 via mma.sync — exact R9 version (proven, 635us)
// ---------------------------------------------------------------------------
#define RSTR 144
#define SA_HI 0
#define SA_LO (128 * RSTR)
#define SW_HI (2 * 128 * RSTR)
#define SW_LO (2 * 128 * RSTR + 64 * RSTR)
#define SMEM_CONV1 (2 * 128 * RSTR + 2 * 64 * RSTR)   // 55296

__global__ __launch_bounds__(256) void conv1_mma(const float* __restrict__ bias)
{
    constexpr int NCH = 14;
    extern __shared__ char smem[];
    const int tid = threadIdx.x;
    const int warp = tid >> 5, lane = tid & 31;
    const int p0 = blockIdx.x * 128;

    const int m = tid >> 1, half = tid & 1;
    const int p = p0 + m;
    const int z = p / DD;
    const int rr = p - z * DD;
    const int y = rr / DIM;
    const int x = rr - y * DIM;

    const int wm = warp >> 1, wn = warp & 1;
    const int g = lane >> 2, tg = lane & 3;

    float acc[2][4][4];
    #pragma unroll
    for (int mt = 0; mt < 2; mt++)
        #pragma unroll
        for (int nt = 0; nt < 4; nt++)
            #pragma unroll
            for (int q = 0; q < 4; q++) acc[mt][nt][q] = 0.f;

    for (int j = 0; j < NCH; j++) {
        __syncthreads();
        {
            int tp = 2 * j + half;
            bool v = (tp <= 26);
            int kz = tp / 9, ky = (tp / 3) % 3, kx = tp % 3;
            v = v && (unsigned)(z + kz - 1) < 80u &&
                     (unsigned)(y + ky - 1) < 80u &&
                     (unsigned)(x + kx - 1) < 80u;
            int ps = p + (kz - 1) * DD + (ky - 1) * DIM + (kx - 1);
            const uint4* shi = (const uint4*)(g_xhi + (size_t)ps * 32);
            const uint4* slo = (const uint4*)(g_xlo + (size_t)ps * 32);
            const uint4 zero = make_uint4(0, 0, 0, 0);
            #pragma unroll
            for (int i = 0; i < 4; i++) {
                u32 off = m * RSTR + half * 64 + i * 16;
                *(uint4*)(smem + SA_HI + off) = v ? shi[i] : zero;
                *(uint4*)(smem + SA_LO + off) = v ? slo[i] : zero;
            }
        }
        {
            const uint4* wh = (const uint4*)(g_w1hi + j * 4096);
            const uint4* wl = (const uint4*)(g_w1lo + j * 4096);
            #pragma unroll
            for (int u = tid; u < 512; u += 256) {
                u32 off = (u >> 3) * RSTR + (u & 7) * 16;
                *(uint4*)(smem + SW_HI + off) = wh[u];
                *(uint4*)(smem + SW_LO + off) = wl[u];
            }
        }
        __syncthreads();

        #pragma unroll
        for (int ks = 0; ks < 4; ks++) {
            u32 ah[2][4], al[2][4];
            #pragma unroll
            for (int mt = 0; mt < 2; mt++) {
                u32 base = (wm * 32 + mt * 16 + g) * RSTR + ks * 32 + tg * 4;
                ah[mt][0] = *(const u32*)(smem + SA_HI + base);
                ah[mt][1] = *(const u32*)(smem + SA_HI + base + 8 * RSTR);
                ah[mt][2] = *(const u32*)(smem + SA_HI + base + 16);
                ah[mt][3] = *(const u32*)(smem + SA_HI + base + 8 * RSTR + 16);
                al[mt][0] = *(const u32*)(smem + SA_LO + base);
                al[mt][1] = *(const u32*)(smem + SA_LO + base + 8 * RSTR);
                al[mt][2] = *(const u32*)(smem + SA_LO + base + 16);
                al[mt][3] = *(const u32*)(smem + SA_LO + base + 8 * RSTR + 16);
            }
            u32 bh[4][2], bl[4][2];
            #pragma unroll
            for (int nt = 0; nt < 4; nt++) {
                u32 base = (wn * 32 + nt * 8 + g) * RSTR + ks * 32 + tg * 4;
                bh[nt][0] = *(const u32*)(smem + SW_HI + base);
                bh[nt][1] = *(const u32*)(smem + SW_HI + base + 16);
                bl[nt][0] = *(const u32*)(smem + SW_LO + base);
                bl[nt][1] = *(const u32*)(smem + SW_LO + base + 16);
            }
            #pragma unroll
            for (int mt = 0; mt < 2; mt++)
                #pragma unroll
                for (int nt = 0; nt < 4; nt++) {
                    mma16816(acc[mt][nt], ah[mt], bh[nt]);
                    mma16816(acc[mt][nt], ah[mt], bl[nt]);
                    mma16816(acc[mt][nt], al[mt], bh[nt]);
                }
        }
    }

    #pragma unroll
    for (int mt = 0; mt < 2; mt++) {
        #pragma unroll
        for (int nt = 0; nt < 4; nt++) {
            const int n = wn * 32 + nt * 8 + tg * 2;
            const float b0 = __ldg(bias + n), b1 = __ldg(bias + n + 1);
            const int pixA = p0 + wm * 32 + mt * 16 + g;
            const int pixB = pixA + 8;
            float v0 = fmaxf(acc[mt][nt][0] + b0, 0.f);
            float v1 = fmaxf(acc[mt][nt][1] + b1, 0.f);
            float v2 = fmaxf(acc[mt][nt][2] + b0, 0.f);
            float v3 = fmaxf(acc[mt][nt][3] + b1, 0.f);
            __nv_bfloat16 h0 = __float2bfloat16_rn(v0);
            __nv_bfloat16 h1 = __float2bfloat16_rn(v1);
            __nv_bfloat16 h2 = __float2bfloat16_rn(v2);
            __nv_bfloat16 h3 = __float2bfloat16_rn(v3);
            *(u32*)(g_f1hi + (size_t)pixA * 64 + n) = pkbf(h0, h1);
            *(u32*)(g_f1hi + (size_t)pixB * 64 + n) = pkbf(h2, h3);
            *(u32*)(g_f1lo + (size_t)pixA * 64 + n) =
                pkbf(__float2bfloat16_rn(v0 - __bfloat162float(h0)),
                     __float2bfloat16_rn(v1 - __bfloat162float(h1)));
            *(u32*)(g_f1lo + (size_t)pixB * 64 + n) =
                pkbf(__float2bfloat16_rn(v2 - __bfloat162float(h2)),
                     __float2bfloat16_rn(v3 - __bfloat162float(h3)));
        }
    }
}

// ---------------------------------------------------------------------------
// Conv2 with halo tiling: stage 130-row A halo once per (kz,ky); the 3 kx
// taps read it at row offset +kx. x-boundary zeros applied at fragment level.
// Smem: A 130x144x2 = 37440 + W 3 taps x 18432 = 92736 B -> 2 CTAs/SM.
// ---------------------------------------------------------------------------
#define AROWS 130
#define A2_HI 0
#define A2_LO (AROWS * RSTR)                  // 18720
#define W2_BASE (2 * AROWS * RSTR)            // 37440
#define W2_TAP (2 * 64 * RSTR)                // 18432
#define SMEM_CONV2 (W2_BASE + 3 * W2_TAP)     // 92736

__global__ __launch_bounds__(256) void conv2_halo(const float* __restrict__ bias)
{
    extern __shared__ char smem[];
    const int tid = threadIdx.x;
    const int warp = tid >> 5, lane = tid & 31;
    const int p0 = blockIdx.x * 128;
    const int wm = warp >> 1, wn = warp & 1;
    const int g = lane >> 2, tg = lane & 3;

    // x coordinate of this lane's two A-fragment rows, per mt
    int xr0[2], xr1[2];
    #pragma unroll
    for (int mt = 0; mt < 2; mt++) {
        int pr = p0 + wm * 32 + mt * 16 + g;
        xr0[mt] = pr % 80;
        xr1[mt] = (pr + 8) % 80;
    }

    float acc[2][4][4];
    #pragma unroll
    for (int mt = 0; mt < 2; mt++)
        #pragma unroll
        for (int nt = 0; nt < 4; nt++)
            #pragma unroll
            for (int q = 0; q < 4; q++) acc[mt][nt][q] = 0.f;

    for (int jzy = 0; jzy < 9; jzy++) {
        const int kz = jzy / 3, ky = jzy - kz * 3;
        __syncthreads();
        // ---- stage A halo: rows 0..129 = pixels p0-1 .. p0+128 (z/y shifted)
        for (int i = tid; i < 2 * AROWS; i += 256) {
            int r = i >> 1, h = i & 1;
            int q = p0 + r - 1;
            bool v = (q >= 0) && (q < D3);
            int zq = 0, yq = 0;
            if (v) { zq = q / DD; int r2 = q - zq * DD; yq = r2 / DIM; }
            v = v && (unsigned)(zq + kz - 1) < 80u &&
                     (unsigned)(yq + ky - 1) < 80u;
            u32 off = r * RSTR + h * 64;
            if (v) {
                int ps = q + (kz - 1) * DD + (ky - 1) * DIM;
                const uint4* shi = (const uint4*)(g_f1hi + (size_t)ps * 64) + h * 4;
                const uint4* slo = (const uint4*)(g_f1lo + (size_t)ps * 64) + h * 4;
                #pragma unroll
                for (int t = 0; t < 4; t++) {
                    *(uint4*)(smem + A2_HI + off + t * 16) = shi[t];
                    *(uint4*)(smem + A2_LO + off + t * 16) = slo[t];
                }
            } else {
                const uint4 zero = make_uint4(0, 0, 0, 0);
                #pragma unroll
                for (int t = 0; t < 4; t++) {
                    *(uint4*)(smem + A2_HI + off + t * 16) = zero;
                    *(uint4*)(smem + A2_LO + off + t * 16) = zero;
                }
            }
        }
        // ---- stage W for the 3 kx taps of this (kz,ky)
        #pragma unroll
        for (int kx = 0; kx < 3; kx++) {
            int j = jzy * 3 + kx;
            const uint4* wh = (const uint4*)(g_w2hi + j * 4096);
            const uint4* wl = (const uint4*)(g_w2lo + j * 4096);
            #pragma unroll
            for (int u = tid; u < 512; u += 256) {
                u32 off = (u >> 3) * RSTR + (u & 7) * 16;
                *(uint4*)(smem + W2_BASE + kx * W2_TAP + off) = wh[u];
                *(uint4*)(smem + W2_BASE + kx * W2_TAP + 9216 + off) = wl[u];
            }
        }
        __syncthreads();

        // ---- compute: 3 kx taps from the shared halo
        #pragma unroll
        for (int kx = 0; kx < 3; kx++) {
            const char* wp = smem + W2_BASE + kx * W2_TAP;
            #pragma unroll
            for (int ks = 0; ks < 4; ks++) {
                u32 bh[4][2], bl[4][2];
                #pragma unroll
                for (int nt = 0; nt < 4; nt++) {
                    u32 base = (wn * 32 + nt * 8 + g) * RSTR + ks * 32 + tg * 4;
                    bh[nt][0] = *(const u32*)(wp + base);
                    bh[nt][1] = *(const u32*)(wp + base + 16);
                    bl[nt][0] = *(const u32*)(wp + 9216 + base);
                    bl[nt][1] = *(const u32*)(wp + 9216 + base + 16);
                }
                #pragma unroll
                for (int mt = 0; mt < 2; mt++) {
                    bool va = (kx == 1) ||
                              (kx == 0 ? (xr0[mt] != 0) : (xr0[mt] != 79));
                    bool vb = (kx == 1) ||
                              (kx == 0 ? (xr1[mt] != 0) : (xr1[mt] != 79));
                    u32 base = (wm * 32 + mt * 16 + g + kx) * RSTR +
                               ks * 32 + tg * 4;
                    u32 ah[4], al[4];
                    ah[0] = va ? *(const u32*)(smem + A2_HI + base) : 0u;
                    ah[1] = vb ? *(const u32*)(smem + A2_HI + base + 8 * RSTR) : 0u;
                    ah[2] = va ? *(const u32*)(smem + A2_HI + base + 16) : 0u;
                    ah[3] = vb ? *(const u32*)(smem + A2_HI + base + 8 * RSTR + 16) : 0u;
                    al[0] = va ? *(const u32*)(smem + A2_LO + base) : 0u;
                    al[1] = vb ? *(const u32*)(smem + A2_LO + base + 8 * RSTR) : 0u;
                    al[2] = va ? *(const u32*)(smem + A2_LO + base + 16) : 0u;
                    al[3] = vb ? *(const u32*)(smem + A2_LO + base + 8 * RSTR + 16) : 0u;
                    #pragma unroll
                    for (int nt = 0; nt < 4; nt++) {
                        mma16816(acc[mt][nt], ah, bh[nt]);
                        mma16816(acc[mt][nt], ah, bl[nt]);
                        mma16816(acc[mt][nt], al, bh[nt]);
                    }
                }
            }
        }
    }

    // ---- epilogue: bias + ReLU, fp32 out (pixel-major)
    #pragma unroll
    for (int mt = 0; mt < 2; mt++) {
        #pragma unroll
        for (int nt = 0; nt < 4; nt++) {
            const int n = wn * 32 + nt * 8 + tg * 2;
            const float b0 = __ldg(bias + n), b1 = __ldg(bias + n + 1);
            const int pixA = p0 + wm * 32 + mt * 16 + g;
            const int pixB = pixA + 8;
            float v0 = fmaxf(acc[mt][nt][0] + b0, 0.f);
            float v1 = fmaxf(acc[mt][nt][1] + b1, 0.f);
            float v2 = fmaxf(acc[mt][nt][2] + b0, 0.f);
            float v3 = fmaxf(acc[mt][nt][3] + b1, 0.f);
            *(float2*)(g_f2 + (size_t)pixA * 64 + n) = make_float2(v0, v1);
            *(float2*)(g_f2 + (size_t)pixB * 64 + n) = make_float2(v2, v3);
        }
    }
}

// ---------------------------------------------------------------------------
// MLP GEMM via mma.sync — unchanged from R9 (proven)
// ---------------------------------------------------------------------------
#define MLP_SA_LO (128 * RSTR)

template<int MODE>
__global__ __launch_bounds__(256) void mlp_gemm(
    const int* __restrict__ c0, const int* __restrict__ c1,
    const int* __restrict__ c2, const float* __restrict__ bias)
{
    constexpr int CIN  = (MODE == 1) ? 64 : 256;
    constexpr int COUT = (MODE == 3) ? 64 : 256;
    constexpr int CTAN = (COUT >= 256) ? 128 : 64;
    constexpr int NT   = CTAN / 16;
    constexpr int SB_HI = 2 * 128 * RSTR;
    constexpr int SB_LO = SB_HI + CTAN * RSTR;

    extern __shared__ char smem[];
    const int tid = threadIdx.x;
    const int warp = tid >> 5, lane = tid & 31;
    const int wm = warp >> 1, wn = warp & 1;
    const int g = lane >> 2, tg = lane & 3;
    const int p0 = blockIdx.x * 128;
    const int n0 = blockIdx.y * CTAN;

    const int m = tid >> 1, half = tid & 1;
    const int row = p0 + m;

    float acc[2][NT][4];
    #pragma unroll
    for (int mt = 0; mt < 2; mt++)
        #pragma unroll
        for (int nt = 0; nt < NT; nt++)
            #pragma unroll
            for (int q = 0; q < 4; q++) acc[mt][nt][q] = 0.f;

    for (int cb = 0; cb < CIN; cb += 64) {
        __syncthreads();
        if (MODE == 1) {
            bool ok = row < NPTS;
            const float4* src = nullptr;
            if (ok) {
                int v = c0[row] * DD + c1[row] * DIM + c2[row];
                src = (const float4*)(g_f2 + (size_t)v * 64 + half * 32);
            }
            u32 hw[16], lw[16];
            #pragma unroll
            for (int i = 0; i < 8; i++) {
                float4 q = ok ? src[i] : make_float4(0.f, 0.f, 0.f, 0.f);
                __nv_bfloat16 ah = __float2bfloat16_rn(q.x);
                __nv_bfloat16 al = __float2bfloat16_rn(q.x - __bfloat162float(ah));
                __nv_bfloat16 bh = __float2bfloat16_rn(q.y);
                __nv_bfloat16 bl = __float2bfloat16_rn(q.y - __bfloat162float(bh));
                hw[2*i]   = pkbf(ah, bh);
                lw[2*i]   = pkbf(al, bl);
                ah = __float2bfloat16_rn(q.z);
                al = __float2bfloat16_rn(q.z - __bfloat162float(ah));
                bh = __float2bfloat16_rn(q.w);
                bl = __float2bfloat16_rn(q.w - __bfloat162float(bh));
                hw[2*i+1] = pkbf(ah, bh);
                lw[2*i+1] = pkbf(al, bl);
            }
            #pragma unroll
            for (int i = 0; i < 4; i++) {
                u32 off = m * RSTR + half * 64 + i * 16;
                *(uint4*)(smem + 0 + off) =
                    make_uint4(hw[4*i], hw[4*i+1], hw[4*i+2], hw[4*i+3]);
                *(uint4*)(smem + MLP_SA_LO + off) =
                    make_uint4(lw[4*i], lw[4*i+1], lw[4*i+2], lw[4*i+3]);
            }
        } else {
            const __nv_bfloat16* Ahi = (MODE == 2) ? g_h1hi : g_h2hi;
            const __nv_bfloat16* Alo = (MODE == 2) ? g_h1lo : g_h2lo;
            const uint4* shi = (const uint4*)(Ahi + (size_t)row * CIN + cb + half * 32);
            const uint4* slo = (const uint4*)(Alo + (size_t)row * CIN + cb + half * 32);
            #pragma unroll
            for (int i = 0; i < 4; i++) {
                u32 off = m * RSTR + half * 64 + i * 16;
                *(uint4*)(smem + 0 + off) = shi[i];
                *(uint4*)(smem + MLP_SA_LO + off) = slo[i];
            }
        }
        {
            const __nv_bfloat16* Whi =
                (MODE == 1) ? g_mw1hi : (MODE == 2) ? g_mw2hi : g_mw3hi;
            const __nv_bfloat16* Wlo =
                (MODE == 1) ? g_mw1lo : (MODE == 2) ? g_mw2lo : g_mw3lo;
            for (int u = tid; u < CTAN * 2; u += 256) {
                int n = u >> 1, h = u & 1;
                const uint4* sh =
                    (const uint4*)(Whi + (size_t)(n0 + n) * CIN + cb + h * 32);
                const uint4* sl =
                    (const uint4*)(Wlo + (size_t)(n0 + n) * CIN + cb + h * 32);
                #pragma unroll
                for (int i = 0; i < 4; i++) {
                    u32 off = n * RSTR + h * 64 + i * 16;
                    *(uint4*)(smem + SB_HI + off) = sh[i];
                    *(uint4*)(smem + SB_LO + off) = sl[i];
                }
            }
        }
        __syncthreads();

        #pragma unroll
        for (int ks = 0; ks < 4; ks++) {
            u32 ah[2][4], al[2][4];
            #pragma unroll
            for (int mt = 0; mt < 2; mt++) {
                u32 base = (wm * 32 + mt * 16 + g) * RSTR + ks * 32 + tg * 4;
                ah[mt][0] = *(const u32*)(smem + 0 + base);
                ah[mt][1] = *(const u32*)(smem + 0 + base + 8 * RSTR);
                ah[mt][2] = *(const u32*)(smem + 0 + base + 16);
                ah[mt][3] = *(const u32*)(smem + 0 + base + 8 * RSTR + 16);
                al[mt][0] = *(const u32*)(smem + MLP_SA_LO + base);
                al[mt][1] = *(const u32*)(smem + MLP_SA_LO + base + 8 * RSTR);
                al[mt][2] = *(const u32*)(smem + MLP_SA_LO + base + 16);
                al[mt][3] = *(const u32*)(smem + MLP_SA_LO + base + 8 * RSTR + 16);
            }
            u32 bh[NT][2], bl[NT][2];
            #pragma unroll
            for (int nt = 0; nt < NT; nt++) {
                u32 base = (wn * (CTAN / 2) + nt * 8 + g) * RSTR + ks * 32 + tg * 4;
                bh[nt][0] = *(const u32*)(smem + SB_HI + base);
                bh[nt][1] = *(const u32*)(smem + SB_HI + base + 16);
                bl[nt][0] = *(const u32*)(smem + SB_LO + base);
                bl[nt][1] = *(const u32*)(smem + SB_LO + base + 16);
            }
            #pragma unroll
            for (int mt = 0; mt < 2; mt++)
                #pragma unroll
                for (int nt = 0; nt < NT; nt++) {
                    mma16816(acc[mt][nt], ah[mt], bh[nt]);
                    mma16816(acc[mt][nt], ah[mt], bl[nt]);
                    mma16816(acc[mt][nt], al[mt], bh[nt]);
                }
        }
    }

    #pragma unroll
    for (int mt = 0; mt < 2; mt++) {
        #pragma unroll
        for (int nt = 0; nt < NT; nt++) {
            const int nl = wn * (CTAN / 2) + nt * 8 + tg * 2;
            const int gc = n0 + nl;
            const float b0 = __ldg(bias + gc), b1 = __ldg(bias + gc + 1);
            const int pixA = p0 + wm * 32 + mt * 16 + g;
            const int pixB = pixA + 8;
            float v0 = acc[mt][nt][0] + b0;
            float v1 = acc[mt][nt][1] + b1;
            float v2 = acc[mt][nt][2] + b0;
            float v3 = acc[mt][nt][3] + b1;
            if (MODE != 3) {
                v0 = fmaxf(v0, 0.f); v1 = fmaxf(v1, 0.f);
                v2 = fmaxf(v2, 0.f); v3 = fmaxf(v3, 0.f);
                __nv_bfloat16* Ohi = (MODE == 1) ? g_h1hi : g_h2hi;
                __nv_bfloat16* Olo = (MODE == 1) ? g_h1lo : g_h2lo;
                __nv_bfloat16 h0 = __float2bfloat16_rn(v0);
                __nv_bfloat16 h1 = __float2bfloat16_rn(v1);
                __nv_bfloat16 h2 = __float2bfloat16_rn(v2);
                __nv_bfloat16 h3 = __float2bfloat16_rn(v3);
                *(u32*)(Ohi + (size_t)pixA * 256 + gc) = pkbf(h0, h1);
                *(u32*)(Ohi + (size_t)pixB * 256 + gc) = pkbf(h2, h3);
                *(u32*)(Olo + (size_t)pixA * 256 + gc) =
                    pkbf(__float2bfloat16_rn(v0 - __bfloat162float(h0)),
                         __float2bfloat16_rn(v1 - __bfloat162float(h1)));
                *(u32*)(Olo + (size_t)pixB * 256 + gc) =
                    pkbf(__float2bfloat16_rn(v2 - __bfloat162float(h2)),
                         __float2bfloat16_rn(v3 - __bfloat162float(h3)));
            } else {
                *(float2*)(g_h3 + (size_t)pixA * 64 + gc) = make_float2(v0, v1);
                *(float2*)(g_h3 + (size_t)pixB * 64 + gc) = make_float2(v2, v3);
            }
        }
    }
}

// ---------------------------------------------------------------------------
// Final layer: out[o][p] = b4[o] + sum_c w4[o][c] * h3[p][c]
// ---------------------------------------------------------------------------
__global__ __launch_bounds__(256) void mlp_l4(
    const float* __restrict__ w4, const float* __restrict__ b4,
    float* __restrict__ out)
{
    __shared__ float ws[384];
    __shared__ float bs[6];
    int tid = threadIdx.x;
    for (int i = tid; i < 384; i += 256) ws[i] = w4[i];
    if (tid < 6) bs[tid] = b4[tid];
    __syncthreads();
    int p = blockIdx.x * 256 + tid;
    if (p >= NPTS) return;
    float h[64];
    const float4* src = (const float4*)(g_h3 + (size_t)p * 64);
    #pragma unroll
    for (int i = 0; i < 16; i++) {
        float4 q = src[i];
        h[4*i] = q.x; h[4*i+1] = q.y; h[4*i+2] = q.z; h[4*i+3] = q.w;
    }
    #pragma unroll
    for (int o = 0; o < 6; o++) {
        float a = bs[o];
        #pragma unroll
        for (int c = 0; c < 64; c++)
            a = fmaf(ws[o * 64 + c], h[c], a);
        out[(size_t)o * NPTS + p] = a;
    }
}

// ---------------------------------------------------------------------------
extern "C" void kernel_launch(void* const* d_in, const int* in_sizes, int n_in,
                              void* d_out, int out_size)
{
    const float* img = (const float*)d_in[0];
    const int*   c0  = (const int*)d_in[1];
    const int*   c1  = (const int*)d_in[2];
    const int*   c2  = (const int*)d_in[3];
    const float* we1 = (const float*)d_in[4];
    const float* be1 = (const float*)d_in[5];
    const float* we2 = (const float*)d_in[6];
    const float* be2 = (const float*)d_in[7];
    const float* wp1 = (const float*)d_in[8];
    const float* bp1 = (const float*)d_in[9];
    const float* wp2 = (const float*)d_in[10];
    const float* bp2 = (const float*)d_in[11];
    const float* wp3 = (const float*)d_in[12];
    const float* bp3 = (const float*)d_in[13];
    const float* wp4 = (const float*)d_in[14];
    const float* bp4 = (const float*)d_in[15];
    float* out = (float*)d_out;

    cudaFuncSetAttribute(conv1_mma,
                         cudaFuncAttributeMaxDynamicSharedMemorySize, SMEM_CONV1);
    cudaFuncSetAttribute(conv2_halo,
                         cudaFuncAttributeMaxDynamicSharedMemorySize, SMEM_CONV2);
    const int smemG1 = 2 * 128 * RSTR + 2 * 128 * RSTR;   // 73728
    const int smemG3 = 2 * 128 * RSTR + 2 * 64 * RSTR;    // 55296
    cudaFuncSetAttribute(mlp_gemm<1>,
                         cudaFuncAttributeMaxDynamicSharedMemorySize, smemG1);
    cudaFuncSetAttribute(mlp_gemm<2>,
                         cudaFuncAttributeMaxDynamicSharedMemorySize, smemG1);
    cudaFuncSetAttribute(mlp_gemm<3>,
                         cudaFuncAttributeMaxDynamicSharedMemorySize, smemG3);

    __nv_bfloat16 *mw1hi, *mw1lo, *mw2hi, *mw2lo, *mw3hi, *mw3lo;
    cudaGetSymbolAddress((void**)&mw1hi, g_mw1hi);
    cudaGetSymbolAddress((void**)&mw1lo, g_mw1lo);
    cudaGetSymbolAddress((void**)&mw2hi, g_mw2hi);
    cudaGetSymbolAddress((void**)&mw2lo, g_mw2lo);
    cudaGetSymbolAddress((void**)&mw3hi, g_mw3hi);
    cudaGetSymbolAddress((void**)&mw3lo, g_mw3lo);

    prep_img<<<2000, 256>>>(img);
    prep_w1<<<(14 * 4096 + 255) / 256, 256>>>(we1);
    prep_w2<<<(27 * 4096 + 255) / 256, 256>>>(we2);
    prep_wmlp<<<(256 * 64 + 255) / 256, 256>>>(wp1, mw1hi, mw1lo, 256 * 64);
    prep_wmlp<<<(256 * 256 + 255) / 256, 256>>>(wp2, mw2hi, mw2lo, 256 * 256);
    prep_wmlp<<<(64 * 256 + 255) / 256, 256>>>(wp3, mw3hi, mw3lo, 64 * 256);

    conv1_mma<<<4000, 256, SMEM_CONV1>>>(be1);
    conv2_halo<<<4000, 256, SMEM_CONV2>>>(be2);

    dim3 g12(NPAD / 128, 2);
    mlp_gemm<1><<<g12, 256, smemG1>>>(c0, c1, c2, bp1);
    mlp_gemm<2><<<g12, 256, smemG1>>>(c0, c1, c2, bp2);
    dim3 g3(NPAD / 128, 1);
    mlp_gemm<3><<<g3, 256, smemG3>>>(c0, c1, c2, bp3);
    mlp_l4<<<(NPTS + 255) / 256, 256>>>(wp4, bp4, out);
}

// round 13
// speedup vs baseline: 1.4546x; 1.0677x over previous
#include <cuda_runtime.h>
#include <cuda_bf16.h>
#include <cstdint>

#define DIM 80
#define DD 6400
#define D3 512000
#define NPTS 200000
#define NPAD 200064   // 1563 * 128

typedef unsigned long long u64;
typedef unsigned int u32;

// ---------------------------------------------------------------------------
// Device scratch (no allocations in kernel_launch)
// ---------------------------------------------------------------------------
__device__ __nv_bfloat16 g_xhi[D3 * 32];
__device__ __nv_bfloat16 g_xlo[D3 * 32];
__device__ __nv_bfloat16 g_f1hi[D3 * 64];
__device__ __nv_bfloat16 g_f1lo[D3 * 64];
__device__ float         g_f2[D3 * 64];
__device__ __nv_bfloat16 g_w1hi[27 * 64 * 32], g_w1lo[27 * 64 * 32]; // [tap][oc][32c]
__device__ __nv_bfloat16 g_w2hi[27 * 64 * 64], g_w2lo[27 * 64 * 64];
// MLP
__device__ __nv_bfloat16 g_h1hi[(size_t)NPAD * 256], g_h1lo[(size_t)NPAD * 256];
__device__ __nv_bfloat16 g_h2hi[(size_t)NPAD * 256], g_h2lo[(size_t)NPAD * 256];
__device__ float         g_h3[(size_t)NPAD * 64];
__device__ __nv_bfloat16 g_mw1hi[256 * 64],  g_mw1lo[256 * 64];
__device__ __nv_bfloat16 g_mw2hi[256 * 256], g_mw2lo[256 * 256];
__device__ __nv_bfloat16 g_mw3hi[64 * 256],  g_mw3lo[64 * 256];

__device__ __forceinline__ u32 pkbf(__nv_bfloat16 a, __nv_bfloat16 b) {
    return (u32)__bfloat16_as_ushort(a) | ((u32)__bfloat16_as_ushort(b) << 16);
}

__device__ __forceinline__ void mma16816(float* d, const u32* a, const u32* b) {
    asm volatile(
        "mma.sync.aligned.m16n8k16.row.col.f32.bf16.bf16.f32 "
        "{%0,%1,%2,%3}, {%4,%5,%6,%7}, {%8,%9}, {%0,%1,%2,%3};"
        : "+f"(d[0]), "+f"(d[1]), "+f"(d[2]), "+f"(d[3])
        : "r"(a[0]), "r"(a[1]), "r"(a[2]), "r"(a[3]), "r"(b[0]), "r"(b[1]));
}

// ---------------------------------------------------------------------------
// Prep kernels
// ---------------------------------------------------------------------------
__global__ void prep_img(const float* __restrict__ img) {
    int p = blockIdx.x * 256 + threadIdx.x;
    u32 hw[16], lw[16];
    #pragma unroll
    for (int c = 0; c < 32; c += 2) {
        float a = img[c * D3 + p];
        float b = img[(c + 1) * D3 + p];
        __nv_bfloat16 ah = __float2bfloat16_rn(a);
        __nv_bfloat16 al = __float2bfloat16_rn(a - __bfloat162float(ah));
        __nv_bfloat16 bh = __float2bfloat16_rn(b);
        __nv_bfloat16 bl = __float2bfloat16_rn(b - __bfloat162float(bh));
        hw[c >> 1] = pkbf(ah, bh);
        lw[c >> 1] = pkbf(al, bl);
    }
    uint4* oh = (uint4*)(g_xhi + (size_t)p * 32);
    uint4* ol = (uint4*)(g_xlo + (size_t)p * 32);
    #pragma unroll
    for (int q = 0; q < 4; q++) {
        oh[q] = make_uint4(hw[q*4], hw[q*4+1], hw[q*4+2], hw[q*4+3]);
        ol[q] = make_uint4(lw[q*4], lw[q*4+1], lw[q*4+2], lw[q*4+3]);
    }
}

// conv1 weights: [27 taps][64 oc][32 c] hi/lo
__global__ void prep_w1(const float* __restrict__ w) {
    int idx = blockIdx.x * 256 + threadIdx.x;
    if (idx >= 27 * 2048) return;
    int j = idx >> 11, r = idx & 2047, o = r >> 5, c = r & 31;
    float v = w[(o * 32 + c) * 27 + j];
    __nv_bfloat16 h = __float2bfloat16_rn(v);
    g_w1hi[idx] = h;
    g_w1lo[idx] = __float2bfloat16_rn(v - __bfloat162float(h));
}
__global__ void prep_w2(const float* __restrict__ w) {
    int idx = blockIdx.x * 256 + threadIdx.x;
    if (idx >= 27 * 4096) return;
    int j = idx >> 12, r = idx & 4095, o = r >> 6, c = r & 63;
    float v = w[(o * 64 + c) * 27 + j];
    __nv_bfloat16 h = __float2bfloat16_rn(v);
    g_w2hi[idx] = h;
    g_w2lo[idx] = __float2bfloat16_rn(v - __bfloat162float(h));
}

__global__ void prep_wmlp(const float* __restrict__ src,
                          __nv_bfloat16* __restrict__ dhi,
                          __nv_bfloat16* __restrict__ dlo, int n) {
    int i = blockIdx.x * 256 + threadIdx.x;
    if (i >= n) return;
    float v = src[i];
    __nv_bfloat16 h = __float2bfloat16_rn(v);
    dhi[i] = h;
    dlo[i] = __float2bfloat16_rn(v - __bfloat162float(h));
}

#define RSTR 144
#define AROWS 130

// ---------------------------------------------------------------------------
// Conv1 with halo tiling (R13). K=32 per tap (2 k16 steps). Smem rows pack
// [hi 64B | lo 64B] in one 144B stride (proven banking).
// A halo: 130 rows x 144B = 18720. W: 3 taps x 64 rows x 144B = 27648.
// Total 46368 B.
// ---------------------------------------------------------------------------
#define C1_W_BASE (AROWS * RSTR)              // 18720
#define C1_W_TAP  (64 * RSTR)                 // 9216
#define SMEM_CONV1 (C1_W_BASE + 3 * C1_W_TAP) // 46368

__global__ __launch_bounds__(256) void conv1_halo(const float* __restrict__ bias)
{
    extern __shared__ char smem[];
    const int tid = threadIdx.x;
    const int warp = tid >> 5, lane = tid & 31;
    const int p0 = blockIdx.x * 128;
    const int wm = warp >> 1, wn = warp & 1;
    const int g = lane >> 2, tg = lane & 3;

    int xr0[2], xr1[2];
    #pragma unroll
    for (int mt = 0; mt < 2; mt++) {
        int pr = p0 + wm * 32 + mt * 16 + g;
        xr0[mt] = pr % 80;
        xr1[mt] = (pr + 8) % 80;
    }

    float acc[2][4][4];
    #pragma unroll
    for (int mt = 0; mt < 2; mt++)
        #pragma unroll
        for (int nt = 0; nt < 4; nt++)
            #pragma unroll
            for (int q = 0; q < 4; q++) acc[mt][nt][q] = 0.f;

    for (int jzy = 0; jzy < 9; jzy++) {
        const int kz = jzy / 3, ky = jzy - kz * 3;
        __syncthreads();
        // ---- stage A halo: 130 rows, each [hi 64B | lo 64B]
        for (int i = tid; i < AROWS * 8; i += 256) {
            int r = i >> 3, t = i & 7;        // t<4: hi quad t, t>=4: lo quad t-4
            int q = p0 + r - 1;
            bool v = (q >= 0) && (q < D3);
            int zq = 0, yq = 0;
            if (v) { zq = q / DD; int r2 = q - zq * DD; yq = r2 / DIM; }
            v = v && (unsigned)(zq + kz - 1) < 80u &&
                     (unsigned)(yq + ky - 1) < 80u;
            u32 off = r * RSTR + ((t & 4) ? 64 : 0) + (t & 3) * 16;
            if (v) {
                int ps = q + (kz - 1) * DD + (ky - 1) * DIM;
                const uint4* src = (t < 4)
                    ? (const uint4*)(g_xhi + (size_t)ps * 32) + t
                    : (const uint4*)(g_xlo + (size_t)ps * 32) + (t - 4);
                *(uint4*)(smem + off) = *src;
            } else {
                *(uint4*)(smem + off) = make_uint4(0, 0, 0, 0);
            }
        }
        // ---- stage W: 3 taps, each 64 rows x [hi 64B | lo 64B]
        #pragma unroll
        for (int kx = 0; kx < 3; kx++) {
            int j = jzy * 3 + kx;
            const uint4* wh = (const uint4*)(g_w1hi + j * 2048);
            const uint4* wl = (const uint4*)(g_w1lo + j * 2048);
            #pragma unroll
            for (int u = tid; u < 512; u += 256) {
                int r = u >> 3, t = u & 7;
                u32 off = C1_W_BASE + kx * C1_W_TAP + r * RSTR +
                          ((t & 4) ? 64 : 0) + (t & 3) * 16;
                *(uint4*)(smem + off) = (t < 4) ? wh[r * 4 + t]
                                                : wl[r * 4 + (t - 4)];
            }
        }
        __syncthreads();

        // ---- compute: 3 kx taps x 2 k16 steps
        #pragma unroll
        for (int kx = 0; kx < 3; kx++) {
            const char* wp = smem + C1_W_BASE + kx * C1_W_TAP;
            #pragma unroll
            for (int ks = 0; ks < 2; ks++) {
                u32 bh[4][2], bl[4][2];
                #pragma unroll
                for (int nt = 0; nt < 4; nt++) {
                    u32 base = (wn * 32 + nt * 8 + g) * RSTR + ks * 32 + tg * 4;
                    bh[nt][0] = *(const u32*)(wp + base);
                    bh[nt][1] = *(const u32*)(wp + base + 16);
                    bl[nt][0] = *(const u32*)(wp + base + 64);
                    bl[nt][1] = *(const u32*)(wp + base + 64 + 16);
                }
                #pragma unroll
                for (int mt = 0; mt < 2; mt++) {
                    bool va = (kx == 1) ||
                              (kx == 0 ? (xr0[mt] != 0) : (xr0[mt] != 79));
                    bool vb = (kx == 1) ||
                              (kx == 0 ? (xr1[mt] != 0) : (xr1[mt] != 79));
                    u32 base = (wm * 32 + mt * 16 + g + kx) * RSTR +
                               ks * 32 + tg * 4;
                    u32 ah[4], al[4];
                    ah[0] = va ? *(const u32*)(smem + base) : 0u;
                    ah[1] = vb ? *(const u32*)(smem + base + 8 * RSTR) : 0u;
                    ah[2] = va ? *(const u32*)(smem + base + 16) : 0u;
                    ah[3] = vb ? *(const u32*)(smem + base + 8 * RSTR + 16) : 0u;
                    al[0] = va ? *(const u32*)(smem + base + 64) : 0u;
                    al[1] = vb ? *(const u32*)(smem + base + 64 + 8 * RSTR) : 0u;
                    al[2] = va ? *(const u32*)(smem + base + 64 + 16) : 0u;
                    al[3] = vb ? *(const u32*)(smem + base + 64 + 8 * RSTR + 16) : 0u;
                    #pragma unroll
                    for (int nt = 0; nt < 4; nt++) {
                        mma16816(acc[mt][nt], ah, bh[nt]);
                        mma16816(acc[mt][nt], ah, bl[nt]);
                        mma16816(acc[mt][nt], al, bh[nt]);
                    }
                }
            }
        }
    }

    // ---- epilogue: bias + ReLU -> g_f1 hi/lo (pixel-major 64ch)
    #pragma unroll
    for (int mt = 0; mt < 2; mt++) {
        #pragma unroll
        for (int nt = 0; nt < 4; nt++) {
            const int n = wn * 32 + nt * 8 + tg * 2;
            const float b0 = __ldg(bias + n), b1 = __ldg(bias + n + 1);
            const int pixA = p0 + wm * 32 + mt * 16 + g;
            const int pixB = pixA + 8;
            float v0 = fmaxf(acc[mt][nt][0] + b0, 0.f);
            float v1 = fmaxf(acc[mt][nt][1] + b1, 0.f);
            float v2 = fmaxf(acc[mt][nt][2] + b0, 0.f);
            float v3 = fmaxf(acc[mt][nt][3] + b1, 0.f);
            __nv_bfloat16 h0 = __float2bfloat16_rn(v0);
            __nv_bfloat16 h1 = __float2bfloat16_rn(v1);
            __nv_bfloat16 h2 = __float2bfloat16_rn(v2);
            __nv_bfloat16 h3 = __float2bfloat16_rn(v3);
            *(u32*)(g_f1hi + (size_t)pixA * 64 + n) = pkbf(h0, h1);
            *(u32*)(g_f1hi + (size_t)pixB * 64 + n) = pkbf(h2, h3);
            *(u32*)(g_f1lo + (size_t)pixA * 64 + n) =
                pkbf(__float2bfloat16_rn(v0 - __bfloat162float(h0)),
                     __float2bfloat16_rn(v1 - __bfloat162float(h1)));
            *(u32*)(g_f1lo + (size_t)pixB * 64 + n) =
                pkbf(__float2bfloat16_rn(v2 - __bfloat162float(h2)),
                     __float2bfloat16_rn(v3 - __bfloat162float(h3)));
        }
    }
}

// ---------------------------------------------------------------------------
// Conv2 with halo tiling — unchanged from R12 (proven)
// ---------------------------------------------------------------------------
#define A2_HI 0
#define A2_LO (AROWS * RSTR)                  // 18720
#define W2_BASE (2 * AROWS * RSTR)            // 37440
#define W2_TAP (2 * 64 * RSTR)                // 18432
#define SMEM_CONV2 (W2_BASE + 3 * W2_TAP)     // 92736

__global__ __launch_bounds__(256) void conv2_halo(const float* __restrict__ bias)
{
    extern __shared__ char smem[];
    const int tid = threadIdx.x;
    const int warp = tid >> 5, lane = tid & 31;
    const int p0 = blockIdx.x * 128;
    const int wm = warp >> 1, wn = warp & 1;
    const int g = lane >> 2, tg = lane & 3;

    int xr0[2], xr1[2];
    #pragma unroll
    for (int mt = 0; mt < 2; mt++) {
        int pr = p0 + wm * 32 + mt * 16 + g;
        xr0[mt] = pr % 80;
        xr1[mt] = (pr + 8) % 80;
    }

    float acc[2][4][4];
    #pragma unroll
    for (int mt = 0; mt < 2; mt++)
        #pragma unroll
        for (int nt = 0; nt < 4; nt++)
            #pragma unroll
            for (int q = 0; q < 4; q++) acc[mt][nt][q] = 0.f;

    for (int jzy = 0; jzy < 9; jzy++) {
        const int kz = jzy / 3, ky = jzy - kz * 3;
        __syncthreads();
        for (int i = tid; i < 2 * AROWS; i += 256) {
            int r = i >> 1, h = i & 1;
            int q = p0 + r - 1;
            bool v = (q >= 0) && (q < D3);
            int zq = 0, yq = 0;
            if (v) { zq = q / DD; int r2 = q - zq * DD; yq = r2 / DIM; }
            v = v && (unsigned)(zq + kz - 1) < 80u &&
                     (unsigned)(yq + ky - 1) < 80u;
            u32 off = r * RSTR + h * 64;
            if (v) {
                int ps = q + (kz - 1) * DD + (ky - 1) * DIM;
                const uint4* shi = (const uint4*)(g_f1hi + (size_t)ps * 64) + h * 4;
                const uint4* slo = (const uint4*)(g_f1lo + (size_t)ps * 64) + h * 4;
                #pragma unroll
                for (int t = 0; t < 4; t++) {
                    *(uint4*)(smem + A2_HI + off + t * 16) = shi[t];
                    *(uint4*)(smem + A2_LO + off + t * 16) = slo[t];
                }
            } else {
                const uint4 zero = make_uint4(0, 0, 0, 0);
                #pragma unroll
                for (int t = 0; t < 4; t++) {
                    *(uint4*)(smem + A2_HI + off + t * 16) = zero;
                    *(uint4*)(smem + A2_LO + off + t * 16) = zero;
                }
            }
        }
        #pragma unroll
        for (int kx = 0; kx < 3; kx++) {
            int j = jzy * 3 + kx;
            const uint4* wh = (const uint4*)(g_w2hi + j * 4096);
            const uint4* wl = (const uint4*)(g_w2lo + j * 4096);
            #pragma unroll
            for (int u = tid; u < 512; u += 256) {
                u32 off = (u >> 3) * RSTR + (u & 7) * 16;
                *(uint4*)(smem + W2_BASE + kx * W2_TAP + off) = wh[u];
                *(uint4*)(smem + W2_BASE + kx * W2_TAP + 9216 + off) = wl[u];
            }
        }
        __syncthreads();

        #pragma unroll
        for (int kx = 0; kx < 3; kx++) {
            const char* wp = smem + W2_BASE + kx * W2_TAP;
            #pragma unroll
            for (int ks = 0; ks < 4; ks++) {
                u32 bh[4][2], bl[4][2];
                #pragma unroll
                for (int nt = 0; nt < 4; nt++) {
                    u32 base = (wn * 32 + nt * 8 + g) * RSTR + ks * 32 + tg * 4;
                    bh[nt][0] = *(const u32*)(wp + base);
                    bh[nt][1] = *(const u32*)(wp + base + 16);
                    bl[nt][0] = *(const u32*)(wp + 9216 + base);
                    bl[nt][1] = *(const u32*)(wp + 9216 + base + 16);
                }
                #pragma unroll
                for (int mt = 0; mt < 2; mt++) {
                    bool va = (kx == 1) ||
                              (kx == 0 ? (xr0[mt] != 0) : (xr0[mt] != 79));
                    bool vb = (kx == 1) ||
                              (kx == 0 ? (xr1[mt] != 0) : (xr1[mt] != 79));
                    u32 base = (wm * 32 + mt * 16 + g + kx) * RSTR +
                               ks * 32 + tg * 4;
                    u32 ah[4], al[4];
                    ah[0] = va ? *(const u32*)(smem + A2_HI + base) : 0u;
                    ah[1] = vb ? *(const u32*)(smem + A2_HI + base + 8 * RSTR) : 0u;
                    ah[2] = va ? *(const u32*)(smem + A2_HI + base + 16) : 0u;
                    ah[3] = vb ? *(const u32*)(smem + A2_HI + base + 8 * RSTR + 16) : 0u;
                    al[0] = va ? *(const u32*)(smem + A2_LO + base) : 0u;
                    al[1] = vb ? *(const u32*)(smem + A2_LO + base + 8 * RSTR) : 0u;
                    al[2] = va ? *(const u32*)(smem + A2_LO + base + 16) : 0u;
                    al[3] = vb ? *(const u32*)(smem + A2_LO + base + 8 * RSTR + 16) : 0u;
                    #pragma unroll
                    for (int nt = 0; nt < 4; nt++) {
                        mma16816(acc[mt][nt], ah, bh[nt]);
                        mma16816(acc[mt][nt], ah, bl[nt]);
                        mma16816(acc[mt][nt], al, bh[nt]);
                    }
                }
            }
        }
    }

    #pragma unroll
    for (int mt = 0; mt < 2; mt++) {
        #pragma unroll
        for (int nt = 0; nt < 4; nt++) {
            const int n = wn * 32 + nt * 8 + tg * 2;
            const float b0 = __ldg(bias + n), b1 = __ldg(bias + n + 1);
            const int pixA = p0 + wm * 32 + mt * 16 + g;
            const int pixB = pixA + 8;
            float v0 = fmaxf(acc[mt][nt][0] + b0, 0.f);
            float v1 = fmaxf(acc[mt][nt][1] + b1, 0.f);
            float v2 = fmaxf(acc[mt][nt][2] + b0, 0.f);
            float v3 = fmaxf(acc[mt][nt][3] + b1, 0.f);
            *(float2*)(g_f2 + (size_t)pixA * 64 + n) = make_float2(v0, v1);
            *(float2*)(g_f2 + (size_t)pixB * 64 + n) = make_float2(v2, v3);
        }
    }
}

// ---------------------------------------------------------------------------
// MLP GEMM via mma.sync — unchanged from R9 (proven)
// ---------------------------------------------------------------------------
#define MLP_SA_LO (128 * RSTR)

template<int MODE>
__global__ __launch_bounds__(256) void mlp_gemm(
    const int* __restrict__ c0, const int* __restrict__ c1,
    const int* __restrict__ c2, const float* __restrict__ bias)
{
    constexpr int CIN  = (MODE == 1) ? 64 : 256;
    constexpr int COUT = (MODE == 3) ? 64 : 256;
    constexpr int CTAN = (COUT >= 256) ? 128 : 64;
    constexpr int NT   = CTAN / 16;
    constexpr int SB_HI = 2 * 128 * RSTR;
    constexpr int SB_LO = SB_HI + CTAN * RSTR;

    extern __shared__ char smem[];
    const int tid = threadIdx.x;
    const int warp = tid >> 5, lane = tid & 31;
    const int wm = warp >> 1, wn = warp & 1;
    const int g = lane >> 2, tg = lane & 3;
    const int p0 = blockIdx.x * 128;
    const int n0 = blockIdx.y * CTAN;

    const int m = tid >> 1, half = tid & 1;
    const int row = p0 + m;

    float acc[2][NT][4];
    #pragma unroll
    for (int mt = 0; mt < 2; mt++)
        #pragma unroll
        for (int nt = 0; nt < NT; nt++)
            #pragma unroll
            for (int q = 0; q < 4; q++) acc[mt][nt][q] = 0.f;

    for (int cb = 0; cb < CIN; cb += 64) {
        __syncthreads();
        if (MODE == 1) {
            bool ok = row < NPTS;
            const float4* src = nullptr;
            if (ok) {
                int v = c0[row] * DD + c1[row] * DIM + c2[row];
                src = (const float4*)(g_f2 + (size_t)v * 64 + half * 32);
            }
            u32 hw[16], lw[16];
            #pragma unroll
            for (int i = 0; i < 8; i++) {
                float4 q = ok ? src[i] : make_float4(0.f, 0.f, 0.f, 0.f);
                __nv_bfloat16 ah = __float2bfloat16_rn(q.x);
                __nv_bfloat16 al = __float2bfloat16_rn(q.x - __bfloat162float(ah));
                __nv_bfloat16 bh = __float2bfloat16_rn(q.y);
                __nv_bfloat16 bl = __float2bfloat16_rn(q.y - __bfloat162float(bh));
                hw[2*i]   = pkbf(ah, bh);
                lw[2*i]   = pkbf(al, bl);
                ah = __float2bfloat16_rn(q.z);
                al = __float2bfloat16_rn(q.z - __bfloat162float(ah));
                bh = __float2bfloat16_rn(q.w);
                bl = __float2bfloat16_rn(q.w - __bfloat162float(bh));
                hw[2*i+1] = pkbf(ah, bh);
                lw[2*i+1] = pkbf(al, bl);
            }
            #pragma unroll
            for (int i = 0; i < 4; i++) {
                u32 off = m * RSTR + half * 64 + i * 16;
                *(uint4*)(smem + 0 + off) =
                    make_uint4(hw[4*i], hw[4*i+1], hw[4*i+2], hw[4*i+3]);
                *(uint4*)(smem + MLP_SA_LO + off) =
                    make_uint4(lw[4*i], lw[4*i+1], lw[4*i+2], lw[4*i+3]);
            }
        } else {
            const __nv_bfloat16* Ahi = (MODE == 2) ? g_h1hi : g_h2hi;
            const __nv_bfloat16* Alo = (MODE == 2) ? g_h1lo : g_h2lo;
            const uint4* shi = (const uint4*)(Ahi + (size_t)row * CIN + cb + half * 32);
            const uint4* slo = (const uint4*)(Alo + (size_t)row * CIN + cb + half * 32);
            #pragma unroll
            for (int i = 0; i < 4; i++) {
                u32 off = m * RSTR + half * 64 + i * 16;
                *(uint4*)(smem + 0 + off) = shi[i];
                *(uint4*)(smem + MLP_SA_LO + off) = slo[i];
            }
        }
        {
            const __nv_bfloat16* Whi =
                (MODE == 1) ? g_mw1hi : (MODE == 2) ? g_mw2hi : g_mw3hi;
            const __nv_bfloat16* Wlo =
                (MODE == 1) ? g_mw1lo : (MODE == 2) ? g_mw2lo : g_mw3lo;
            for (int u = tid; u < CTAN * 2; u += 256) {
                int n = u >> 1, h = u & 1;
                const uint4* sh =
                    (const uint4*)(Whi + (size_t)(n0 + n) * CIN + cb + h * 32);
                const uint4* sl =
                    (const uint4*)(Wlo + (size_t)(n0 + n) * CIN + cb + h * 32);
                #pragma unroll
                for (int i = 0; i < 4; i++) {
                    u32 off = n * RSTR + h * 64 + i * 16;
                    *(uint4*)(smem + SB_HI + off) = sh[i];
                    *(uint4*)(smem + SB_LO + off) = sl[i];
                }
            }
        }
        __syncthreads();

        #pragma unroll
        for (int ks = 0; ks < 4; ks++) {
            u32 ah[2][4], al[2][4];
            #pragma unroll
            for (int mt = 0; mt < 2; mt++) {
                u32 base = (wm * 32 + mt * 16 + g) * RSTR + ks * 32 + tg * 4;
                ah[mt][0] = *(const u32*)(smem + 0 + base);
                ah[mt][1] = *(const u32*)(smem + 0 + base + 8 * RSTR);
                ah[mt][2] = *(const u32*)(smem + 0 + base + 16);
                ah[mt][3] = *(const u32*)(smem + 0 + base + 8 * RSTR + 16);
                al[mt][0] = *(const u32*)(smem + MLP_SA_LO + base);
                al[mt][1] = *(const u32*)(smem + MLP_SA_LO + base + 8 * RSTR);
                al[mt][2] = *(const u32*)(smem + MLP_SA_LO + base + 16);
                al[mt][3] = *(const u32*)(smem + MLP_SA_LO + base + 8 * RSTR + 16);
            }
            u32 bh[NT][2], bl[NT][2];
            #pragma unroll
            for (int nt = 0; nt < NT; nt++) {
                u32 base = (wn * (CTAN / 2) + nt * 8 + g) * RSTR + ks * 32 + tg * 4;
                bh[nt][0] = *(const u32*)(smem + SB_HI + base);
                bh[nt][1] = *(const u32*)(smem + SB_HI + base + 16);
                bl[nt][0] = *(const u32*)(smem + SB_LO + base);
                bl[nt][1] = *(const u32*)(smem + SB_LO + base + 16);
            }
            #pragma unroll
            for (int mt = 0; mt < 2; mt++)
                #pragma unroll
                for (int nt = 0; nt < NT; nt++) {
                    mma16816(acc[mt][nt], ah[mt], bh[nt]);
                    mma16816(acc[mt][nt], ah[mt], bl[nt]);
                    mma16816(acc[mt][nt], al[mt], bh[nt]);
                }
        }
    }

    #pragma unroll
    for (int mt = 0; mt < 2; mt++) {
        #pragma unroll
        for (int nt = 0; nt < NT; nt++) {
            const int nl = wn * (CTAN / 2) + nt * 8 + tg * 2;
            const int gc = n0 + nl;
            const float b0 = __ldg(bias + gc), b1 = __ldg(bias + gc + 1);
            const int pixA = p0 + wm * 32 + mt * 16 + g;
            const int pixB = pixA + 8;
            float v0 = acc[mt][nt][0] + b0;
            float v1 = acc[mt][nt][1] + b1;
            float v2 = acc[mt][nt][2] + b0;
            float v3 = acc[mt][nt][3] + b1;
            if (MODE != 3) {
                v0 = fmaxf(v0, 0.f); v1 = fmaxf(v1, 0.f);
                v2 = fmaxf(v2, 0.f); v3 = fmaxf(v3, 0.f);
                __nv_bfloat16* Ohi = (MODE == 1) ? g_h1hi : g_h2hi;
                __nv_bfloat16* Olo = (MODE == 1) ? g_h1lo : g_h2lo;
                __nv_bfloat16 h0 = __float2bfloat16_rn(v0);
                __nv_bfloat16 h1 = __float2bfloat16_rn(v1);
                __nv_bfloat16 h2 = __float2bfloat16_rn(v2);
                __nv_bfloat16 h3 = __float2bfloat16_rn(v3);
                *(u32*)(Ohi + (size_t)pixA * 256 + gc) = pkbf(h0, h1);
                *(u32*)(Ohi + (size_t)pixB * 256 + gc) = pkbf(h2, h3);
                *(u32*)(Olo + (size_t)pixA * 256 + gc) =
                    pkbf(__float2bfloat16_rn(v0 - __bfloat162float(h0)),
                         __float2bfloat16_rn(v1 - __bfloat162float(h1)));
                *(u32*)(Olo + (size_t)pixB * 256 + gc) =
                    pkbf(__float2bfloat16_rn(v2 - __bfloat162float(h2)),
                         __float2bfloat16_rn(v3 - __bfloat162float(h3)));
            } else {
                *(float2*)(g_h3 + (size_t)pixA * 64 + gc) = make_float2(v0, v1);
                *(float2*)(g_h3 + (size_t)pixB * 64 + gc) = make_float2(v2, v3);
            }
        }
    }
}

// ---------------------------------------------------------------------------
// Final layer: out[o][p] = b4[o] + sum_c w4[o][c] * h3[p][c]
// ---------------------------------------------------------------------------
__global__ __launch_bounds__(256) void mlp_l4(
    const float* __restrict__ w4, const float* __restrict__ b4,
    float* __restrict__ out)
{
    __shared__ float ws[384];
    __shared__ float bs[6];
    int tid = threadIdx.x;
    for (int i = tid; i < 384; i += 256) ws[i] = w4[i];
    if (tid < 6) bs[tid] = b4[tid];
    __syncthreads();
    int p = blockIdx.x * 256 + tid;
    if (p >= NPTS) return;
    float h[64];
    const float4* src = (const float4*)(g_h3 + (size_t)p * 64);
    #pragma unroll
    for (int i = 0; i < 16; i++) {
        float4 q = src[i];
        h[4*i] = q.x; h[4*i+1] = q.y; h[4*i+2] = q.z; h[4*i+3] = q.w;
    }
    #pragma unroll
    for (int o = 0; o < 6; o++) {
        float a = bs[o];
        #pragma unroll
        for (int c = 0; c < 64; c++)
            a = fmaf(ws[o * 64 + c], h[c], a);
        out[(size_t)o * NPTS + p] = a;
    }
}

// ---------------------------------------------------------------------------
extern "C" void kernel_launch(void* const* d_in, const int* in_sizes, int n_in,
                              void* d_out, int out_size)
{
    const float* img = (const float*)d_in[0];
    const int*   c0  = (const int*)d_in[1];
    const int*   c1  = (const int*)d_in[2];
    const int*   c2  = (const int*)d_in[3];
    const float* we1 = (const float*)d_in[4];
    const float* be1 = (const float*)d_in[5];
    const float* we2 = (const float*)d_in[6];
    const float* be2 = (const float*)d_in[7];
    const float* wp1 = (const float*)d_in[8];
    const float* bp1 = (const float*)d_in[9];
    const float* wp2 = (const float*)d_in[10];
    const float* bp2 = (const float*)d_in[11];
    const float* wp3 = (const float*)d_in[12];
    const float* bp3 = (const float*)d_in[13];
    const float* wp4 = (const float*)d_in[14];
    const float* bp4 = (const float*)d_in[15];
    float* out = (float*)d_out;

    cudaFuncSetAttribute(conv1_halo,
                         cudaFuncAttributeMaxDynamicSharedMemorySize, SMEM_CONV1);
    cudaFuncSetAttribute(conv2_halo,
                         cudaFuncAttributeMaxDynamicSharedMemorySize, SMEM_CONV2);
    const int smemG1 = 2 * 128 * RSTR + 2 * 128 * RSTR;   // 73728
    const int smemG3 = 2 * 128 * RSTR + 2 * 64 * RSTR;    // 55296
    cudaFuncSetAttribute(mlp_gemm<1>,
                         cudaFuncAttributeMaxDynamicSharedMemorySize, smemG1);
    cudaFuncSetAttribute(mlp_gemm<2>,
                         cudaFuncAttributeMaxDynamicSharedMemorySize, smemG1);
    cudaFuncSetAttribute(mlp_gemm<3>,
                         cudaFuncAttributeMaxDynamicSharedMemorySize, smemG3);

    __nv_bfloat16 *mw1hi, *mw1lo, *mw2hi, *mw2lo, *mw3hi, *mw3lo;
    cudaGetSymbolAddress((void**)&mw1hi, g_mw1hi);
    cudaGetSymbolAddress((void**)&mw1lo, g_mw1lo);
    cudaGetSymbolAddress((void**)&mw2hi, g_mw2hi);
    cudaGetSymbolAddress((void**)&mw2lo, g_mw2lo);
    cudaGetSymbolAddress((void**)&mw3hi, g_mw3hi);
    cudaGetSymbolAddress((void**)&mw3lo, g_mw3lo);

    prep_img<<<2000, 256>>>(img);
    prep_w1<<<(27 * 2048 + 255) / 256, 256>>>(we1);
    prep_w2<<<(27 * 4096 + 255) / 256, 256>>>(we2);
    prep_wmlp<<<(256 * 64 + 255) / 256, 256>>>(wp1, mw1hi, mw1lo, 256 * 64);
    prep_wmlp<<<(256 * 256 + 255) / 256, 256>>>(wp2, mw2hi, mw2lo, 256 * 256);
    prep_wmlp<<<(64 * 256 + 255) / 256, 256>>>(wp3, mw3hi, mw3lo, 64 * 256);

    conv1_halo<<<4000, 256, SMEM_CONV1>>>(be1);
    conv2_halo<<<4000, 256, SMEM_CONV2>>>(be2);

    dim3 g12(NPAD / 128, 2);
    mlp_gemm<1><<<g12, 256, smemG1>>>(c0, c1, c2, bp1);
    mlp_gemm<2><<<g12, 256, smemG1>>>(c0, c1, c2, bp2);
    dim3 g3(NPAD / 128, 1);
    mlp_gemm<3><<<g3, 256, smemG3>>>(c0, c1, c2, bp3);
    mlp_l4<<<(NPTS + 255) / 256, 256>>>(wp4, bp4, out);
}

// round 14
// speedup vs baseline: 1.4648x; 1.0070x over previous
#include <cuda_runtime.h>
#include <cuda_bf16.h>
#include <cstdint>

#define DIM 80
#define DD 6400
#define D3 512000
#define NPTS 200000
#define NPAD 200064   // 1563 * 128

typedef unsigned long long u64;
typedef unsigned int u32;

// ---------------------------------------------------------------------------
// Device scratch (no allocations in kernel_launch)
// ---------------------------------------------------------------------------
__device__ __nv_bfloat16 g_xhi[D3 * 32];
__device__ __nv_bfloat16 g_xlo[D3 * 32];
__device__ __nv_bfloat16 g_f1hi[D3 * 64];
__device__ __nv_bfloat16 g_f1lo[D3 * 64];
__device__ float         g_f2[D3 * 64];
__device__ __nv_bfloat16 g_w1hi[27 * 64 * 32], g_w1lo[27 * 64 * 32]; // [tap][oc][32c]
__device__ __nv_bfloat16 g_w2hi[27 * 64 * 64], g_w2lo[27 * 64 * 64];
// MLP
__device__ __nv_bfloat16 g_h1hi[(size_t)NPAD * 256], g_h1lo[(size_t)NPAD * 256];
__device__ __nv_bfloat16 g_h2hi[(size_t)NPAD * 256], g_h2lo[(size_t)NPAD * 256];
__device__ float         g_h3[(size_t)NPAD * 64];
__device__ __nv_bfloat16 g_mw1hi[256 * 64],  g_mw1lo[256 * 64];
__device__ __nv_bfloat16 g_mw2hi[256 * 256], g_mw2lo[256 * 256];
__device__ __nv_bfloat16 g_mw3hi[64 * 256],  g_mw3lo[64 * 256];

__device__ __forceinline__ u32 pkbf(__nv_bfloat16 a, __nv_bfloat16 b) {
    return (u32)__bfloat16_as_ushort(a) | ((u32)__bfloat16_as_ushort(b) << 16);
}

__device__ __forceinline__ void mma16816(float* d, const u32* a, const u32* b) {
    asm volatile(
        "mma.sync.aligned.m16n8k16.row.col.f32.bf16.bf16.f32 "
        "{%0,%1,%2,%3}, {%4,%5,%6,%7}, {%8,%9}, {%0,%1,%2,%3};"
        : "+f"(d[0]), "+f"(d[1]), "+f"(d[2]), "+f"(d[3])
        : "r"(a[0]), "r"(a[1]), "r"(a[2]), "r"(a[3]), "r"(b[0]), "r"(b[1]));
}

// ---------------------------------------------------------------------------
// Prep kernels
// ---------------------------------------------------------------------------
__global__ void prep_img(const float* __restrict__ img) {
    int p = blockIdx.x * 256 + threadIdx.x;
    u32 hw[16], lw[16];
    #pragma unroll
    for (int c = 0; c < 32; c += 2) {
        float a = img[c * D3 + p];
        float b = img[(c + 1) * D3 + p];
        __nv_bfloat16 ah = __float2bfloat16_rn(a);
        __nv_bfloat16 al = __float2bfloat16_rn(a - __bfloat162float(ah));
        __nv_bfloat16 bh = __float2bfloat16_rn(b);
        __nv_bfloat16 bl = __float2bfloat16_rn(b - __bfloat162float(bh));
        hw[c >> 1] = pkbf(ah, bh);
        lw[c >> 1] = pkbf(al, bl);
    }
    uint4* oh = (uint4*)(g_xhi + (size_t)p * 32);
    uint4* ol = (uint4*)(g_xlo + (size_t)p * 32);
    #pragma unroll
    for (int q = 0; q < 4; q++) {
        oh[q] = make_uint4(hw[q*4], hw[q*4+1], hw[q*4+2], hw[q*4+3]);
        ol[q] = make_uint4(lw[q*4], lw[q*4+1], lw[q*4+2], lw[q*4+3]);
    }
}

// conv1 weights: [27 taps][64 oc][32 c] hi/lo
__global__ void prep_w1(const float* __restrict__ w) {
    int idx = blockIdx.x * 256 + threadIdx.x;
    if (idx >= 27 * 2048) return;
    int j = idx >> 11, r = idx & 2047, o = r >> 5, c = r & 31;
    float v = w[(o * 32 + c) * 27 + j];
    __nv_bfloat16 h = __float2bfloat16_rn(v);
    g_w1hi[idx] = h;
    g_w1lo[idx] = __float2bfloat16_rn(v - __bfloat162float(h));
}
__global__ void prep_w2(const float* __restrict__ w) {
    int idx = blockIdx.x * 256 + threadIdx.x;
    if (idx >= 27 * 4096) return;
    int j = idx >> 12, r = idx & 4095, o = r >> 6, c = r & 63;
    float v = w[(o * 64 + c) * 27 + j];
    __nv_bfloat16 h = __float2bfloat16_rn(v);
    g_w2hi[idx] = h;
    g_w2lo[idx] = __float2bfloat16_rn(v - __bfloat162float(h));
}

__global__ void prep_wmlp(const float* __restrict__ src,
                          __nv_bfloat16* __restrict__ dhi,
                          __nv_bfloat16* __restrict__ dlo, int n) {
    int i = blockIdx.x * 256 + threadIdx.x;
    if (i >= n) return;
    float v = src[i];
    __nv_bfloat16 h = __float2bfloat16_rn(v);
    dhi[i] = h;
    dlo[i] = __float2bfloat16_rn(v - __bfloat162float(h));
}

#define RSTR 144
#define AROWS 130

// ---------------------------------------------------------------------------
// Conv1 with halo tiling — R13 version + launch_bounds(256,3) for 3 CTAs/SM.
// ---------------------------------------------------------------------------
#define C1_W_BASE (AROWS * RSTR)              // 18720
#define C1_W_TAP  (64 * RSTR)                 // 9216
#define SMEM_CONV1 (C1_W_BASE + 3 * C1_W_TAP) // 46368

__global__ __launch_bounds__(256, 3) void conv1_halo(const float* __restrict__ bias)
{
    extern __shared__ char smem[];
    const int tid = threadIdx.x;
    const int warp = tid >> 5, lane = tid & 31;
    const int p0 = blockIdx.x * 128;
    const int wm = warp >> 1, wn = warp & 1;
    const int g = lane >> 2, tg = lane & 3;

    int xr0[2], xr1[2];
    #pragma unroll
    for (int mt = 0; mt < 2; mt++) {
        int pr = p0 + wm * 32 + mt * 16 + g;
        xr0[mt] = pr % 80;
        xr1[mt] = (pr + 8) % 80;
    }

    float acc[2][4][4];
    #pragma unroll
    for (int mt = 0; mt < 2; mt++)
        #pragma unroll
        for (int nt = 0; nt < 4; nt++)
            #pragma unroll
            for (int q = 0; q < 4; q++) acc[mt][nt][q] = 0.f;

    for (int jzy = 0; jzy < 9; jzy++) {
        const int kz = jzy / 3, ky = jzy - kz * 3;
        __syncthreads();
        for (int i = tid; i < AROWS * 8; i += 256) {
            int r = i >> 3, t = i & 7;
            int q = p0 + r - 1;
            bool v = (q >= 0) && (q < D3);
            int zq = 0, yq = 0;
            if (v) { zq = q / DD; int r2 = q - zq * DD; yq = r2 / DIM; }
            v = v && (unsigned)(zq + kz - 1) < 80u &&
                     (unsigned)(yq + ky - 1) < 80u;
            u32 off = r * RSTR + ((t & 4) ? 64 : 0) + (t & 3) * 16;
            if (v) {
                int ps = q + (kz - 1) * DD + (ky - 1) * DIM;
                const uint4* src = (t < 4)
                    ? (const uint4*)(g_xhi + (size_t)ps * 32) + t
                    : (const uint4*)(g_xlo + (size_t)ps * 32) + (t - 4);
                *(uint4*)(smem + off) = *src;
            } else {
                *(uint4*)(smem + off) = make_uint4(0, 0, 0, 0);
            }
        }
        #pragma unroll
        for (int kx = 0; kx < 3; kx++) {
            int j = jzy * 3 + kx;
            const uint4* wh = (const uint4*)(g_w1hi + j * 2048);
            const uint4* wl = (const uint4*)(g_w1lo + j * 2048);
            #pragma unroll
            for (int u = tid; u < 512; u += 256) {
                int r = u >> 3, t = u & 7;
                u32 off = C1_W_BASE + kx * C1_W_TAP + r * RSTR +
                          ((t & 4) ? 64 : 0) + (t & 3) * 16;
                *(uint4*)(smem + off) = (t < 4) ? wh[r * 4 + t]
                                                : wl[r * 4 + (t - 4)];
            }
        }
        __syncthreads();

        #pragma unroll
        for (int kx = 0; kx < 3; kx++) {
            const char* wp = smem + C1_W_BASE + kx * C1_W_TAP;
            #pragma unroll
            for (int ks = 0; ks < 2; ks++) {
                u32 bh[4][2], bl[4][2];
                #pragma unroll
                for (int nt = 0; nt < 4; nt++) {
                    u32 base = (wn * 32 + nt * 8 + g) * RSTR + ks * 32 + tg * 4;
                    bh[nt][0] = *(const u32*)(wp + base);
                    bh[nt][1] = *(const u32*)(wp + base + 16);
                    bl[nt][0] = *(const u32*)(wp + base + 64);
                    bl[nt][1] = *(const u32*)(wp + base + 64 + 16);
                }
                #pragma unroll
                for (int mt = 0; mt < 2; mt++) {
                    bool va = (kx == 1) ||
                              (kx == 0 ? (xr0[mt] != 0) : (xr0[mt] != 79));
                    bool vb = (kx == 1) ||
                              (kx == 0 ? (xr1[mt] != 0) : (xr1[mt] != 79));
                    u32 base = (wm * 32 + mt * 16 + g + kx) * RSTR +
                               ks * 32 + tg * 4;
                    u32 ah[4], al[4];
                    ah[0] = va ? *(const u32*)(smem + base) : 0u;
                    ah[1] = vb ? *(const u32*)(smem + base + 8 * RSTR) : 0u;
                    ah[2] = va ? *(const u32*)(smem + base + 16) : 0u;
                    ah[3] = vb ? *(const u32*)(smem + base + 8 * RSTR + 16) : 0u;
                    al[0] = va ? *(const u32*)(smem + base + 64) : 0u;
                    al[1] = vb ? *(const u32*)(smem + base + 64 + 8 * RSTR) : 0u;
                    al[2] = va ? *(const u32*)(smem + base + 64 + 16) : 0u;
                    al[3] = vb ? *(const u32*)(smem + base + 64 + 8 * RSTR + 16) : 0u;
                    #pragma unroll
                    for (int nt = 0; nt < 4; nt++) {
                        mma16816(acc[mt][nt], ah, bh[nt]);
                        mma16816(acc[mt][nt], ah, bl[nt]);
                        mma16816(acc[mt][nt], al, bh[nt]);
                    }
                }
            }
        }
    }

    #pragma unroll
    for (int mt = 0; mt < 2; mt++) {
        #pragma unroll
        for (int nt = 0; nt < 4; nt++) {
            const int n = wn * 32 + nt * 8 + tg * 2;
            const float b0 = __ldg(bias + n), b1 = __ldg(bias + n + 1);
            const int pixA = p0 + wm * 32 + mt * 16 + g;
            const int pixB = pixA + 8;
            float v0 = fmaxf(acc[mt][nt][0] + b0, 0.f);
            float v1 = fmaxf(acc[mt][nt][1] + b1, 0.f);
            float v2 = fmaxf(acc[mt][nt][2] + b0, 0.f);
            float v3 = fmaxf(acc[mt][nt][3] + b1, 0.f);
            __nv_bfloat16 h0 = __float2bfloat16_rn(v0);
            __nv_bfloat16 h1 = __float2bfloat16_rn(v1);
            __nv_bfloat16 h2 = __float2bfloat16_rn(v2);
            __nv_bfloat16 h3 = __float2bfloat16_rn(v3);
            *(u32*)(g_f1hi + (size_t)pixA * 64 + n) = pkbf(h0, h1);
            *(u32*)(g_f1hi + (size_t)pixB * 64 + n) = pkbf(h2, h3);
            *(u32*)(g_f1lo + (size_t)pixA * 64 + n) =
                pkbf(__float2bfloat16_rn(v0 - __bfloat162float(h0)),
                     __float2bfloat16_rn(v1 - __bfloat162float(h1)));
            *(u32*)(g_f1lo + (size_t)pixB * 64 + n) =
                pkbf(__float2bfloat16_rn(v2 - __bfloat162float(h2)),
                     __float2bfloat16_rn(v3 - __bfloat162float(h3)));
        }
    }
}

// ---------------------------------------------------------------------------
// Conv2 halo + 2-slot W double buffer (R14): smem 74304 -> 3 CTAs/SM.
// Schedule per (kz,ky): [sync] stage A + W(kx0)->s0 + W(kx1)->s1 [sync]
//                       compute kx0, kx1 [sync] stage W(kx2)->s0 [sync] kx2.
// ---------------------------------------------------------------------------
#define A2_HI 0
#define A2_LO (AROWS * RSTR)                  // 18720
#define W2_BASE (2 * AROWS * RSTR)            // 37440
#define W2_TAP (2 * 64 * RSTR)                // 18432
#define SMEM_CONV2 (W2_BASE + 2 * W2_TAP)     // 74304

__device__ __forceinline__ void c2_stage_w(char* smem, int j, int slot, int tid)
{
    const uint4* wh = (const uint4*)(g_w2hi + j * 4096);
    const uint4* wl = (const uint4*)(g_w2lo + j * 4096);
    #pragma unroll
    for (int u = tid; u < 512; u += 256) {
        u32 off = (u >> 3) * RSTR + (u & 7) * 16;
        *(uint4*)(smem + W2_BASE + slot * W2_TAP + off) = wh[u];
        *(uint4*)(smem + W2_BASE + slot * W2_TAP + 9216 + off) = wl[u];
    }
}

__global__ __launch_bounds__(256, 3) void conv2_halo(const float* __restrict__ bias)
{
    extern __shared__ char smem[];
    const int tid = threadIdx.x;
    const int warp = tid >> 5, lane = tid & 31;
    const int p0 = blockIdx.x * 128;
    const int wm = warp >> 1, wn = warp & 1;
    const int g = lane >> 2, tg = lane & 3;

    int xr0[2], xr1[2];
    #pragma unroll
    for (int mt = 0; mt < 2; mt++) {
        int pr = p0 + wm * 32 + mt * 16 + g;
        xr0[mt] = pr % 80;
        xr1[mt] = (pr + 8) % 80;
    }

    float acc[2][4][4];
    #pragma unroll
    for (int mt = 0; mt < 2; mt++)
        #pragma unroll
        for (int nt = 0; nt < 4; nt++)
            #pragma unroll
            for (int q = 0; q < 4; q++) acc[mt][nt][q] = 0.f;

    for (int jzy = 0; jzy < 9; jzy++) {
        const int kz = jzy / 3, ky = jzy - kz * 3;
        __syncthreads();
        // ---- stage A halo + W taps kx0/kx1
        for (int i = tid; i < 2 * AROWS; i += 256) {
            int r = i >> 1, h = i & 1;
            int q = p0 + r - 1;
            bool v = (q >= 0) && (q < D3);
            int zq = 0, yq = 0;
            if (v) { zq = q / DD; int r2 = q - zq * DD; yq = r2 / DIM; }
            v = v && (unsigned)(zq + kz - 1) < 80u &&
                     (unsigned)(yq + ky - 1) < 80u;
            u32 off = r * RSTR + h * 64;
            if (v) {
                int ps = q + (kz - 1) * DD + (ky - 1) * DIM;
                const uint4* shi = (const uint4*)(g_f1hi + (size_t)ps * 64) + h * 4;
                const uint4* slo = (const uint4*)(g_f1lo + (size_t)ps * 64) + h * 4;
                #pragma unroll
                for (int t = 0; t < 4; t++) {
                    *(uint4*)(smem + A2_HI + off + t * 16) = shi[t];
                    *(uint4*)(smem + A2_LO + off + t * 16) = slo[t];
                }
            } else {
                const uint4 zero = make_uint4(0, 0, 0, 0);
                #pragma unroll
                for (int t = 0; t < 4; t++) {
                    *(uint4*)(smem + A2_HI + off + t * 16) = zero;
                    *(uint4*)(smem + A2_LO + off + t * 16) = zero;
                }
            }
        }
        c2_stage_w(smem, jzy * 3 + 0, 0, tid);
        c2_stage_w(smem, jzy * 3 + 1, 1, tid);
        __syncthreads();

        #pragma unroll
        for (int phase = 0; phase < 2; phase++) {
            // phase 0: kx = 0 (slot0), kx = 1 (slot1); phase 1: kx = 2 (slot0)
            const int nkx = (phase == 0) ? 2 : 1;
            for (int s = 0; s < nkx; s++) {
                const int kx = (phase == 0) ? s : 2;
                const char* wp = smem + W2_BASE + ((phase == 0) ? s : 0) * W2_TAP;
                #pragma unroll
                for (int ks = 0; ks < 4; ks++) {
                    u32 bh[4][2], bl[4][2];
                    #pragma unroll
                    for (int nt = 0; nt < 4; nt++) {
                        u32 base = (wn * 32 + nt * 8 + g) * RSTR + ks * 32 + tg * 4;
                        bh[nt][0] = *(const u32*)(wp + base);
                        bh[nt][1] = *(const u32*)(wp + base + 16);
                        bl[nt][0] = *(const u32*)(wp + 9216 + base);
                        bl[nt][1] = *(const u32*)(wp + 9216 + base + 16);
                    }
                    #pragma unroll
                    for (int mt = 0; mt < 2; mt++) {
                        bool va = (kx == 1) ||
                                  (kx == 0 ? (xr0[mt] != 0) : (xr0[mt] != 79));
                        bool vb = (kx == 1) ||
                                  (kx == 0 ? (xr1[mt] != 0) : (xr1[mt] != 79));
                        u32 base = (wm * 32 + mt * 16 + g + kx) * RSTR +
                                   ks * 32 + tg * 4;
                        u32 ah[4], al[4];
                        ah[0] = va ? *(const u32*)(smem + A2_HI + base) : 0u;
                        ah[1] = vb ? *(const u32*)(smem + A2_HI + base + 8 * RSTR) : 0u;
                        ah[2] = va ? *(const u32*)(smem + A2_HI + base + 16) : 0u;
                        ah[3] = vb ? *(const u32*)(smem + A2_HI + base + 8 * RSTR + 16) : 0u;
                        al[0] = va ? *(const u32*)(smem + A2_LO + base) : 0u;
                        al[1] = vb ? *(const u32*)(smem + A2_LO + base + 8 * RSTR) : 0u;
                        al[2] = va ? *(const u32*)(smem + A2_LO + base + 16) : 0u;
                        al[3] = vb ? *(const u32*)(smem + A2_LO + base + 8 * RSTR + 16) : 0u;
                        #pragma unroll
                        for (int nt = 0; nt < 4; nt++) {
                            mma16816(acc[mt][nt], ah, bh[nt]);
                            mma16816(acc[mt][nt], ah, bl[nt]);
                            mma16816(acc[mt][nt], al, bh[nt]);
                        }
                    }
                }
            }
            if (phase == 0) {
                __syncthreads();
                c2_stage_w(smem, jzy * 3 + 2, 0, tid);
                __syncthreads();
            }
        }
    }

    #pragma unroll
    for (int mt = 0; mt < 2; mt++) {
        #pragma unroll
        for (int nt = 0; nt < 4; nt++) {
            const int n = wn * 32 + nt * 8 + tg * 2;
            const float b0 = __ldg(bias + n), b1 = __ldg(bias + n + 1);
            const int pixA = p0 + wm * 32 + mt * 16 + g;
            const int pixB = pixA + 8;
            float v0 = fmaxf(acc[mt][nt][0] + b0, 0.f);
            float v1 = fmaxf(acc[mt][nt][1] + b1, 0.f);
            float v2 = fmaxf(acc[mt][nt][2] + b0, 0.f);
            float v3 = fmaxf(acc[mt][nt][3] + b1, 0.f);
            *(float2*)(g_f2 + (size_t)pixA * 64 + n) = make_float2(v0, v1);
            *(float2*)(g_f2 + (size_t)pixB * 64 + n) = make_float2(v2, v3);
        }
    }
}

// ---------------------------------------------------------------------------
// MLP GEMM via mma.sync — unchanged from R9 (proven)
// ---------------------------------------------------------------------------
#define MLP_SA_LO (128 * RSTR)

template<int MODE>
__global__ __launch_bounds__(256) void mlp_gemm(
    const int* __restrict__ c0, const int* __restrict__ c1,
    const int* __restrict__ c2, const float* __restrict__ bias)
{
    constexpr int CIN  = (MODE == 1) ? 64 : 256;
    constexpr int COUT = (MODE == 3) ? 64 : 256;
    constexpr int CTAN = (COUT >= 256) ? 128 : 64;
    constexpr int NT   = CTAN / 16;
    constexpr int SB_HI = 2 * 128 * RSTR;
    constexpr int SB_LO = SB_HI + CTAN * RSTR;

    extern __shared__ char smem[];
    const int tid = threadIdx.x;
    const int warp = tid >> 5, lane = tid & 31;
    const int wm = warp >> 1, wn = warp & 1;
    const int g = lane >> 2, tg = lane & 3;
    const int p0 = blockIdx.x * 128;
    const int n0 = blockIdx.y * CTAN;

    const int m = tid >> 1, half = tid & 1;
    const int row = p0 + m;

    float acc[2][NT][4];
    #pragma unroll
    for (int mt = 0; mt < 2; mt++)
        #pragma unroll
        for (int nt = 0; nt < NT; nt++)
            #pragma unroll
            for (int q = 0; q < 4; q++) acc[mt][nt][q] = 0.f;

    for (int cb = 0; cb < CIN; cb += 64) {
        __syncthreads();
        if (MODE == 1) {
            bool ok = row < NPTS;
            const float4* src = nullptr;
            if (ok) {
                int v = c0[row] * DD + c1[row] * DIM + c2[row];
                src = (const float4*)(g_f2 + (size_t)v * 64 + half * 32);
            }
            u32 hw[16], lw[16];
            #pragma unroll
            for (int i = 0; i < 8; i++) {
                float4 q = ok ? src[i] : make_float4(0.f, 0.f, 0.f, 0.f);
                __nv_bfloat16 ah = __float2bfloat16_rn(q.x);
                __nv_bfloat16 al = __float2bfloat16_rn(q.x - __bfloat162float(ah));
                __nv_bfloat16 bh = __float2bfloat16_rn(q.y);
                __nv_bfloat16 bl = __float2bfloat16_rn(q.y - __bfloat162float(bh));
                hw[2*i]   = pkbf(ah, bh);
                lw[2*i]   = pkbf(al, bl);
                ah = __float2bfloat16_rn(q.z);
                al = __float2bfloat16_rn(q.z - __bfloat162float(ah));
                bh = __float2bfloat16_rn(q.w);
                bl = __float2bfloat16_rn(q.w - __bfloat162float(bh));
                hw[2*i+1] = pkbf(ah, bh);
                lw[2*i+1] = pkbf(al, bl);
            }
            #pragma unroll
            for (int i = 0; i < 4; i++) {
                u32 off = m * RSTR + half * 64 + i * 16;
                *(uint4*)(smem + 0 + off) =
                    make_uint4(hw[4*i], hw[4*i+1], hw[4*i+2], hw[4*i+3]);
                *(uint4*)(smem + MLP_SA_LO + off) =
                    make_uint4(lw[4*i], lw[4*i+1], lw[4*i+2], lw[4*i+3]);
            }
        } else {
            const __nv_bfloat16* Ahi = (MODE == 2) ? g_h1hi : g_h2hi;
            const __nv_bfloat16* Alo = (MODE == 2) ? g_h1lo : g_h2lo;
            const uint4* shi = (const uint4*)(Ahi + (size_t)row * CIN + cb + half * 32);
            const uint4* slo = (const uint4*)(Alo + (size_t)row * CIN + cb + half * 32);
            #pragma unroll
            for (int i = 0; i < 4; i++) {
                u32 off = m * RSTR + half * 64 + i * 16;
                *(uint4*)(smem + 0 + off) = shi[i];
                *(uint4*)(smem + MLP_SA_LO + off) = slo[i];
            }
        }
        {
            const __nv_bfloat16* Whi =
                (MODE == 1) ? g_mw1hi : (MODE == 2) ? g_mw2hi : g_mw3hi;
            const __nv_bfloat16* Wlo =
                (MODE == 1) ? g_mw1lo : (MODE == 2) ? g_mw2lo : g_mw3lo;
            for (int u = tid; u < CTAN * 2; u += 256) {
                int n = u >> 1, h = u & 1;
                const uint4* sh =
                    (const uint4*)(Whi + (size_t)(n0 + n) * CIN + cb + h * 32);
                const uint4* sl =
                    (const uint4*)(Wlo + (size_t)(n0 + n) * CIN + cb + h * 32);
                #pragma unroll
                for (int i = 0; i < 4; i++) {
                    u32 off = n * RSTR + h * 64 + i * 16;
                    *(uint4*)(smem + SB_HI + off) = sh[i];
                    *(uint4*)(smem + SB_LO + off) = sl[i];
                }
            }
        }
        __syncthreads();

        #pragma unroll
        for (int ks = 0; ks < 4; ks++) {
            u32 ah[2][4], al[2][4];
            #pragma unroll
            for (int mt = 0; mt < 2; mt++) {
                u32 base = (wm * 32 + mt * 16 + g) * RSTR + ks * 32 + tg * 4;
                ah[mt][0] = *(const u32*)(smem + 0 + base);
                ah[mt][1] = *(const u32*)(smem + 0 + base + 8 * RSTR);
                ah[mt][2] = *(const u32*)(smem + 0 + base + 16);
                ah[mt][3] = *(const u32*)(smem + 0 + base + 8 * RSTR + 16);
                al[mt][0] = *(const u32*)(smem + MLP_SA_LO + base);
                al[mt][1] = *(const u32*)(smem + MLP_SA_LO + base + 8 * RSTR);
                al[mt][2] = *(const u32*)(smem + MLP_SA_LO + base + 16);
                al[mt][3] = *(const u32*)(smem + MLP_SA_LO + base + 8 * RSTR + 16);
            }
            u32 bh[NT][2], bl[NT][2];
            #pragma unroll
            for (int nt = 0; nt < NT; nt++) {
                u32 base = (wn * (CTAN / 2) + nt * 8 + g) * RSTR + ks * 32 + tg * 4;
                bh[nt][0] = *(const u32*)(smem + SB_HI + base);
                bh[nt][1] = *(const u32*)(smem + SB_HI + base + 16);
                bl[nt][0] = *(const u32*)(smem + SB_LO + base);
                bl[nt][1] = *(const u32*)(smem + SB_LO + base + 16);
            }
            #pragma unroll
            for (int mt = 0; mt < 2; mt++)
                #pragma unroll
                for (int nt = 0; nt < NT; nt++) {
                    mma16816(acc[mt][nt], ah[mt], bh[nt]);
                    mma16816(acc[mt][nt], ah[mt], bl[nt]);
                    mma16816(acc[mt][nt], al[mt], bh[nt]);
                }
        }
    }

    #pragma unroll
    for (int mt = 0; mt < 2; mt++) {
        #pragma unroll
        for (int nt = 0; nt < NT; nt++) {
            const int nl = wn * (CTAN / 2) + nt * 8 + tg * 2;
            const int gc = n0 + nl;
            const float b0 = __ldg(bias + gc), b1 = __ldg(bias + gc + 1);
            const int pixA = p0 + wm * 32 + mt * 16 + g;
            const int pixB = pixA + 8;
            float v0 = acc[mt][nt][0] + b0;
            float v1 = acc[mt][nt][1] + b1;
            float v2 = acc[mt][nt][2] + b0;
            float v3 = acc[mt][nt][3] + b1;
            if (MODE != 3) {
                v0 = fmaxf(v0, 0.f); v1 = fmaxf(v1, 0.f);
                v2 = fmaxf(v2, 0.f); v3 = fmaxf(v3, 0.f);
                __nv_bfloat16* Ohi = (MODE == 1) ? g_h1hi : g_h2hi;
                __nv_bfloat16* Olo = (MODE == 1) ? g_h1lo : g_h2lo;
                __nv_bfloat16 h0 = __float2bfloat16_rn(v0);
                __nv_bfloat16 h1 = __float2bfloat16_rn(v1);
                __nv_bfloat16 h2 = __float2bfloat16_rn(v2);
                __nv_bfloat16 h3 = __float2bfloat16_rn(v3);
                *(u32*)(Ohi + (size_t)pixA * 256 + gc) = pkbf(h0, h1);
                *(u32*)(Ohi + (size_t)pixB * 256 + gc) = pkbf(h2, h3);
                *(u32*)(Olo + (size_t)pixA * 256 + gc) =
                    pkbf(__float2bfloat16_rn(v0 - __bfloat162float(h0)),
                         __float2bfloat16_rn(v1 - __bfloat162float(h1)));
                *(u32*)(Olo + (size_t)pixB * 256 + gc) =
                    pkbf(__float2bfloat16_rn(v2 - __bfloat162float(h2)),
                         __float2bfloat16_rn(v3 - __bfloat162float(h3)));
            } else {
                *(float2*)(g_h3 + (size_t)pixA * 64 + gc) = make_float2(v0, v1);
                *(float2*)(g_h3 + (size_t)pixB * 64 + gc) = make_float2(v2, v3);
            }
        }
    }
}

// ---------------------------------------------------------------------------
// Final layer: out[o][p] = b4[o] + sum_c w4[o][c] * h3[p][c]
// ---------------------------------------------------------------------------
__global__ __launch_bounds__(256) void mlp_l4(
    const float* __restrict__ w4, const float* __restrict__ b4,
    float* __restrict__ out)
{
    __shared__ float ws[384];
    __shared__ float bs[6];
    int tid = threadIdx.x;
    for (int i = tid; i < 384; i += 256) ws[i] = w4[i];
    if (tid < 6) bs[tid] = b4[tid];
    __syncthreads();
    int p = blockIdx.x * 256 + tid;
    if (p >= NPTS) return;
    float h[64];
    const float4* src = (const float4*)(g_h3 + (size_t)p * 64);
    #pragma unroll
    for (int i = 0; i < 16; i++) {
        float4 q = src[i];
        h[4*i] = q.x; h[4*i+1] = q.y; h[4*i+2] = q.z; h[4*i+3] = q.w;
    }
    #pragma unroll
    for (int o = 0; o < 6; o++) {
        float a = bs[o];
        #pragma unroll
        for (int c = 0; c < 64; c++)
            a = fmaf(ws[o * 64 + c], h[c], a);
        out[(size_t)o * NPTS + p] = a;
    }
}

// ---------------------------------------------------------------------------
extern "C" void kernel_launch(void* const* d_in, const int* in_sizes, int n_in,
                              void* d_out, int out_size)
{
    const float* img = (const float*)d_in[0];
    const int*   c0  = (const int*)d_in[1];
    const int*   c1  = (const int*)d_in[2];
    const int*   c2  = (const int*)d_in[3];
    const float* we1 = (const float*)d_in[4];
    const float* be1 = (const float*)d_in[5];
    const float* we2 = (const float*)d_in[6];
    const float* be2 = (const float*)d_in[7];
    const float* wp1 = (const float*)d_in[8];
    const float* bp1 = (const float*)d_in[9];
    const float* wp2 = (const float*)d_in[10];
    const float* bp2 = (const float*)d_in[11];
    const float* wp3 = (const float*)d_in[12];
    const float* bp3 = (const float*)d_in[13];
    const float* wp4 = (const float*)d_in[14];
    const float* bp4 = (const float*)d_in[15];
    float* out = (float*)d_out;

    cudaFuncSetAttribute(conv1_halo,
                         cudaFuncAttributeMaxDynamicSharedMemorySize, SMEM_CONV1);
    cudaFuncSetAttribute(conv2_halo,
                         cudaFuncAttributeMaxDynamicSharedMemorySize, SMEM_CONV2);
    const int smemG1 = 2 * 128 * RSTR + 2 * 128 * RSTR;   // 73728
    const int smemG3 = 2 * 128 * RSTR + 2 * 64 * RSTR;    // 55296
    cudaFuncSetAttribute(mlp_gemm<1>,
                         cudaFuncAttributeMaxDynamicSharedMemorySize, smemG1);
    cudaFuncSetAttribute(mlp_gemm<2>,
                         cudaFuncAttributeMaxDynamicSharedMemorySize, smemG1);
    cudaFuncSetAttribute(mlp_gemm<3>,
                         cudaFuncAttributeMaxDynamicSharedMemorySize, smemG3);

    __nv_bfloat16 *mw1hi, *mw1lo, *mw2hi, *mw2lo, *mw3hi, *mw3lo;
    cudaGetSymbolAddress((void**)&mw1hi, g_mw1hi);
    cudaGetSymbolAddress((void**)&mw1lo, g_mw1lo);
    cudaGetSymbolAddress((void**)&mw2hi, g_mw2hi);
    cudaGetSymbolAddress((void**)&mw2lo, g_mw2lo);
    cudaGetSymbolAddress((void**)&mw3hi, g_mw3hi);
    cudaGetSymbolAddress((void**)&mw3lo, g_mw3lo);

    prep_img<<<2000, 256>>>(img);
    prep_w1<<<(27 * 2048 + 255) / 256, 256>>>(we1);
    prep_w2<<<(27 * 4096 + 255) / 256, 256>>>(we2);
    prep_wmlp<<<(256 * 64 + 255) / 256, 256>>>(wp1, mw1hi, mw1lo, 256 * 64);
    prep_wmlp<<<(256 * 256 + 255) / 256, 256>>>(wp2, mw2hi, mw2lo, 256 * 256);
    prep_wmlp<<<(64 * 256 + 255) / 256, 256>>>(wp3, mw3hi, mw3lo, 64 * 256);

    conv1_halo<<<4000, 256, SMEM_CONV1>>>(be1);
    conv2_halo<<<4000, 256, SMEM_CONV2>>>(be2);

    dim3 g12(NPAD / 128, 2);
    mlp_gemm<1><<<g12, 256, smemG1>>>(c0, c1, c2, bp1);
    mlp_gemm<2><<<g12, 256, smemG1>>>(c0, c1, c2, bp2);
    dim3 g3(NPAD / 128, 1);
    mlp_gemm<3><<<g3, 256, smemG3>>>(c0, c1, c2, bp3);
    mlp_l4<<<(NPTS + 255) / 256, 256>>>(wp4, bp4, out);
}